// round 1
// baseline (speedup 1.0000x reference)
#include <cuda_runtime.h>
#include <math.h>

// Problem constants
#define BB 16
#define SS 2048
#define HH 1024
#define FF 1024
#define MM (BB*SS)   // 32768

// Scratch (device globals; no allocations allowed)
__device__ float g_C[(size_t)MM * FF];   // relu(X@W_C + b_C)
__device__ float g_q[BB * FF];
__device__ float g_t1[BB * FF];
__device__ float g_pre[BB * SS];         // energy@v accumulator (alpha pre-softmax)
__device__ float g_alpha[BB * SS];
__device__ float g_Lpre[BB * SS];

// ---------------------------------------------------------------------------
// zero small scratch + h region of d_out
__global__ void zero_kernel(float* q, float* h_out, float* pre, float* lpre) {
    int i = blockIdx.x * 256 + threadIdx.x;     // grid covers 32768
    if (i < BB * FF) { q[i] = 0.f; h_out[i] = 0.f; }
    if (i < BB * SS) { pre[i] = 0.f; lpre[i] = 0.f; }
}

// ---------------------------------------------------------------------------
// SGEMM 128x128x16, 256 threads, 8x8 per-thread tile.
// MODE 0: out = relu(A@B + bias)
// MODE 1: e = tanh(A@B + t1[batch] + bias); atomicAdd(rowdot[row], e . vvec)
template <int MODE>
__global__ void __launch_bounds__(256, 2)
gemm128(const float* __restrict__ A, const float* __restrict__ B,
        const float* __restrict__ bias, float* __restrict__ out,
        const float* __restrict__ t1, const float* __restrict__ vvec,
        float* __restrict__ rowdot)
{
    const int N = FF, K = HH;
    __shared__ float As[16][128];
    __shared__ float Bs[16][128];

    int tid = threadIdx.x;
    int bm = blockIdx.y, bn = blockIdx.x;
    const float* Ablk = A + (size_t)bm * 128 * K;
    const float* Bblk = B + bn * 128;

    int arow = tid >> 2;            // 0..63
    int acol = (tid & 3) * 4;       // 0,4,8,12
    int brow = tid >> 5;            // 0..7
    int bcol = (tid & 31) * 4;      // 0..124

    float acc[8][8];
    #pragma unroll
    for (int i = 0; i < 8; i++)
        #pragma unroll
        for (int j = 0; j < 8; j++) acc[i][j] = 0.f;

    int ty = tid >> 4, tx = tid & 15;

    for (int k0 = 0; k0 < K; k0 += 16) {
        #pragma unroll
        for (int i = 0; i < 2; i++) {
            int r = arow + i * 64;
            float4 a = *(const float4*)(Ablk + (size_t)r * K + k0 + acol);
            As[acol + 0][r] = a.x; As[acol + 1][r] = a.y;
            As[acol + 2][r] = a.z; As[acol + 3][r] = a.w;
        }
        #pragma unroll
        for (int i = 0; i < 2; i++) {
            int r = brow + i * 8;
            float4 b = *(const float4*)(Bblk + (size_t)(k0 + r) * N + bcol);
            *(float4*)&Bs[r][bcol] = b;
        }
        __syncthreads();

        #pragma unroll
        for (int k = 0; k < 16; k++) {
            float4 a0 = *(const float4*)&As[k][ty * 8];
            float4 a1 = *(const float4*)&As[k][ty * 8 + 4];
            float4 b0 = *(const float4*)&Bs[k][tx * 8];
            float4 b1 = *(const float4*)&Bs[k][tx * 8 + 4];
            float ra[8] = {a0.x, a0.y, a0.z, a0.w, a1.x, a1.y, a1.z, a1.w};
            float rb[8] = {b0.x, b0.y, b0.z, b0.w, b1.x, b1.y, b1.z, b1.w};
            #pragma unroll
            for (int i = 0; i < 8; i++)
                #pragma unroll
                for (int j = 0; j < 8; j++)
                    acc[i][j] = fmaf(ra[i], rb[j], acc[i][j]);
        }
        __syncthreads();
    }

    int row0 = bm * 128 + ty * 8;
    int col0 = bn * 128 + tx * 8;

    if (MODE == 0) {
        #pragma unroll
        for (int i = 0; i < 8; i++) {
            #pragma unroll
            for (int j = 0; j < 8; j++) {
                float vv = acc[i][j] + bias[col0 + j];
                out[(size_t)(row0 + i) * N + col0 + j] = vv > 0.f ? vv : 0.f;
            }
        }
    } else {
        int batch = row0 >> 11;  // S=2048; block's 128 rows share a batch
        #pragma unroll
        for (int i = 0; i < 8; i++) {
            float p = 0.f;
            #pragma unroll
            for (int j = 0; j < 8; j++) {
                int col = col0 + j;
                float e = tanhf(acc[i][j] + t1[batch * FF + col] + bias[col]);
                p = fmaf(e, vvec[col], p);
            }
            // reduce across the 16 lanes (same ty) holding this row
            #pragma unroll
            for (int off = 8; off >= 1; off >>= 1)
                p += __shfl_down_sync(0xffffffffu, p, off, 16);
            if (tx == 0) atomicAdd(&rowdot[row0 + i], p);
        }
    }
}

// ---------------------------------------------------------------------------
// out[b,f] += sum_s X[b,s,f] * w[b,s]   (grid: (F/256, B, 8) — s split, atomic)
__global__ void colreduce_kernel(const float* __restrict__ X,
                                 const float* __restrict__ w,
                                 float* __restrict__ out)
{
    int f = blockIdx.x * 256 + threadIdx.x;
    int b = blockIdx.y;
    int s0 = blockIdx.z * 256;
    const float* Xp = X + ((size_t)b * SS + s0) * FF + f;
    const float* wp = w + b * SS + s0;
    float acc = 0.f;
    #pragma unroll 4
    for (int s = 0; s < 256; s++)
        acc = fmaf(Xp[(size_t)s * FF], wp[s], acc);
    atomicAdd(&out[b * FF + f], acc);
}

// ---------------------------------------------------------------------------
// t1[b,n] = sum_k q[b,k] * w1[k,n]   (grid: (F/256, B))
__global__ void smallgemm_kernel(const float* __restrict__ q,
                                 const float* __restrict__ w1,
                                 float* __restrict__ t1)
{
    __shared__ float qs[256];
    int n = blockIdx.x * 256 + threadIdx.x;
    int b = blockIdx.y;
    float acc = 0.f;
    for (int k0 = 0; k0 < FF; k0 += 256) {
        __syncthreads();
        qs[threadIdx.x] = q[b * FF + k0 + threadIdx.x];
        __syncthreads();
        #pragma unroll 8
        for (int k = 0; k < 256; k++)
            acc = fmaf(qs[k], w1[(size_t)(k0 + k) * FF + n], acc);
    }
    t1[b * FF + n] = acc;
}

// ---------------------------------------------------------------------------
__device__ __forceinline__ float blockReduce(float v, bool do_max) {
    __shared__ float sm[32];
    __syncthreads();
    int lane = threadIdx.x & 31, wid = threadIdx.x >> 5;
    #pragma unroll
    for (int o = 16; o; o >>= 1) {
        float t = __shfl_down_sync(0xffffffffu, v, o);
        v = do_max ? fmaxf(v, t) : v + t;
    }
    if (lane == 0) sm[wid] = v;
    __syncthreads();
    int nw = blockDim.x >> 5;
    v = (threadIdx.x < nw) ? sm[threadIdx.x] : (do_max ? -1e30f : 0.f);
    if (wid == 0) {
        #pragma unroll
        for (int o = 16; o; o >>= 1) {
            float t = __shfl_down_sync(0xffffffffu, v, o);
            v = do_max ? fmaxf(v, t) : v + t;
        }
        if (lane == 0) sm[0] = v;
    }
    __syncthreads();
    return sm[0];
}

// softmax over S per batch, with attend mask add. 256 threads, 8 elems/thread.
__global__ void softmax_kernel(const float* __restrict__ pre,
                               const float* __restrict__ mask,
                               float* __restrict__ alpha)
{
    int b = blockIdx.x, tid = threadIdx.x;
    float z[8];
    float mx = -1e30f;
    #pragma unroll
    for (int i = 0; i < 8; i++) {
        int s = tid + i * 256;
        z[i] = pre[b * SS + s] + (1.f - mask[b * SS + s]) * -10000.f;
        mx = fmaxf(mx, z[i]);
    }
    mx = blockReduce(mx, true);
    float sum = 0.f;
    #pragma unroll
    for (int i = 0; i < 8; i++) { z[i] = expf(z[i] - mx); sum += z[i]; }
    sum = blockReduce(sum, false);
    float inv = 1.f / sum;
    #pragma unroll
    for (int i = 0; i < 8; i++)
        alpha[b * SS + tid + i * 256] = z[i] * inv;
}

// ---------------------------------------------------------------------------
// sparsemax over S per batch. 1024 threads/block, one block per batch.
__global__ void sparsemax_kernel(const float* __restrict__ Lpre,
                                 const float* __restrict__ mask,
                                 const float* __restrict__ w_1,
                                 const float* __restrict__ w_2,
                                 const float* __restrict__ w_3,
                                 const int* __restrict__ layer_i,
                                 float* __restrict__ Lout)
{
    __shared__ float zs[SS];
    __shared__ float cum[SS];
    __shared__ int scnt;
    int b = blockIdx.x, tid = threadIdx.x;

    int li = layer_i[0];
    float a1 = w_1[0], a2 = w_2[0], a3 = w_3[0];
    float x;
    if (li == 0)      x = a3 * a3 - a2 * a2 - a1 * a1;
    else if (li == 1) x = a3 * a3 - a2 * a2;
    else              x = a3 * a3;
    float sig = 1.f / (1.f + expf(-x));

    for (int i = tid; i < SS; i += 1024)
        zs[i] = Lpre[b * SS + i] * sig + (1.f - mask[b * SS + i]) * -10000.f;
    if (tid == 0) scnt = 0;
    __syncthreads();

    // bitonic sort ascending (read back reversed for descending)
    for (int k = 2; k <= SS; k <<= 1) {
        for (int j = k >> 1; j > 0; j >>= 1) {
            for (int t = tid; t < SS; t += 1024) {
                int ixj = t ^ j;
                if (ixj > t) {
                    float a = zs[t], c = zs[ixj];
                    bool up = ((t & k) == 0);
                    if ((a > c) == up) { zs[t] = c; zs[ixj] = a; }
                }
            }
            __syncthreads();
        }
    }

    // cum[i] = prefix sum of descending-sorted values
    cum[tid]        = zs[SS - 1 - tid];
    cum[tid + 1024] = zs[SS - 1 - (tid + 1024)];
    __syncthreads();
    for (int off = 1; off < SS; off <<= 1) {
        float v0 = (tid >= off) ? cum[tid - off] : 0.f;
        float v1 = cum[tid + 1024 - off];
        __syncthreads();
        cum[tid] += v0;
        cum[tid + 1024] += v1;
        __syncthreads();
    }

    // support count: (1 + k * z_sorted[k-1]) > cum[k-1]
    int c = 0;
    #pragma unroll
    for (int r = 0; r < 2; r++) {
        int i = tid + r * 1024;
        if (1.f + (float)(i + 1) * zs[SS - 1 - i] > cum[i]) c++;
    }
    atomicAdd(&scnt, c);
    __syncthreads();
    int ks = scnt;
    float tau = (cum[ks - 1] - 1.f) / (float)ks;

    for (int i = tid; i < SS; i += 1024) {
        float zv = Lpre[b * SS + i] * sig + (1.f - mask[b * SS + i]) * -10000.f;
        Lout[b * SS + i] = fmaxf(zv - tau, 0.f);
    }
}

// ---------------------------------------------------------------------------
extern "C" void kernel_launch(void* const* d_in, const int* in_sizes, int n_in,
                              void* d_out, int out_size)
{
    const float* mask      = (const float*)d_in[0];
    const float* X         = (const float*)d_in[1];
    const float* iw        = (const float*)d_in[2];
    const float* W_C       = (const float*)d_in[3];
    const float* b_C       = (const float*)d_in[4];
    const float* W_A       = (const float*)d_in[5];
    const float* b_A       = (const float*)d_in[6];
    const float* w1        = (const float*)d_in[7];
    const float* w2        = (const float*)d_in[8];
    const float* attn_bias = (const float*)d_in[9];
    const float* v         = (const float*)d_in[10];
    const float* w_1       = (const float*)d_in[11];
    const float* w_2s      = (const float*)d_in[12];
    const float* w_3       = (const float*)d_in[13];
    const int*   layer_i   = (const int*)d_in[14];

    float* out   = (float*)d_out;
    float* h_out = out;                          // [B,F,1]   16384
    float* L_out = out + BB * FF;                // [B,S,1]   32768
    float* A_out = out + BB * FF + BB * SS;      // [B,S,F]   33554432

    float *pC, *pq, *pt1, *ppre, *palpha, *pLpre;
    cudaGetSymbolAddress((void**)&pC,     g_C);
    cudaGetSymbolAddress((void**)&pq,     g_q);
    cudaGetSymbolAddress((void**)&pt1,    g_t1);
    cudaGetSymbolAddress((void**)&ppre,   g_pre);
    cudaGetSymbolAddress((void**)&palpha, g_alpha);
    cudaGetSymbolAddress((void**)&pLpre,  g_Lpre);

    dim3 gemmGrid(FF / 128, MM / 128);

    // 0) zero accumulators (g_q, h_out, g_pre, g_Lpre)
    zero_kernel<<<128, 256>>>(pq, h_out, ppre, pLpre);
    // 1) C = relu(X @ W_C + b_C)
    gemm128<0><<<gemmGrid, 256>>>(X, W_C, b_C, pC, nullptr, nullptr, nullptr);
    // 2) A = relu(X @ W_A + b_A)  -> straight to output
    gemm128<0><<<gemmGrid, 256>>>(X, W_A, b_A, A_out, nullptr, nullptr, nullptr);
    // 3) q[b,f] = sum_s C * item_weights
    colreduce_kernel<<<dim3(FF / 256, BB, 8), 256>>>(pC, iw, pq);
    // 4) t1 = q @ w1
    smallgemm_kernel<<<dim3(FF / 256, BB), 256>>>(pq, w1, pt1);
    // 5) alpha_pre[b,s] = tanh(C@w2 + t1 + bias) . v
    gemm128<1><<<gemmGrid, 256>>>(pC, w2, attn_bias, nullptr, pt1, v, ppre);
    // 6) alpha = softmax(alpha_pre + mask_add)
    softmax_kernel<<<BB, 256>>>(ppre, mask, palpha);
    // 7) h[b,f] = sum_s C * alpha  -> straight to output (also consumed below)
    colreduce_kernel<<<dim3(FF / 256, BB, 8), 256>>>(pC, palpha, h_out);
    // 8) t1 = h @ w1
    smallgemm_kernel<<<dim3(FF / 256, BB), 256>>>(h_out, w1, pt1);
    // 9) L_pre[b,s] = tanh(A@w2 + t1 + bias) . v
    gemm128<1><<<gemmGrid, 256>>>(A_out, w2, attn_bias, nullptr, pt1, v, pLpre);
    // 10) L = sparsemax(L_pre * sigmoid(x) + mask_add)
    sparsemax_kernel<<<BB, 1024>>>(pLpre, mask, w_1, w_2s, w_3, layer_i, L_out);
}

// round 3
// speedup vs baseline: 2.1349x; 2.1349x over previous
#include <cuda_runtime.h>
#include <cuda_bf16.h>
#include <math.h>
#include <stdint.h>

#define BB 16
#define SS 2048
#define HH 1024
#define FF 1024
#define MM (BB*SS)   // 32768

// ---------------- device scratch (no runtime allocation allowed) ----------
__device__ __nv_bfloat16 g_Xh[(size_t)MM*HH], g_Xl[(size_t)MM*HH];
__device__ __nv_bfloat16 g_Ch[(size_t)MM*FF], g_Cl[(size_t)MM*FF];
__device__ __nv_bfloat16 g_Ahm[(size_t)MM*FF], g_Alm[(size_t)MM*FF];
__device__ __nv_bfloat16 g_WCh[(size_t)FF*HH], g_WCl[(size_t)FF*HH];
__device__ __nv_bfloat16 g_WAh[(size_t)FF*HH], g_WAl[(size_t)FF*HH];
__device__ __nv_bfloat16 g_W2h[(size_t)FF*FF], g_W2l[(size_t)FF*FF];
__device__ float g_q[BB*FF];
__device__ float g_t1[BB*FF];
__device__ float g_pre[BB*SS];
__device__ float g_alpha[BB*SS];
__device__ float g_Lpre[BB*SS];

// ---------------------------------------------------------------------------
__device__ __forceinline__ void split2(float x, __nv_bfloat16& h, __nv_bfloat16& l) {
    h = __float2bfloat16(x);
    l = __float2bfloat16(x - __bfloat162float(h));
}

__device__ __forceinline__ void cpa16(uint32_t s, const void* g) {
    asm volatile("cp.async.cg.shared.global [%0], [%1], 16;" :: "r"(s), "l"(g));
}
__device__ __forceinline__ void cp_commit() {
    asm volatile("cp.async.commit_group;");
}
__device__ __forceinline__ void ldsm4(uint32_t* r, uint32_t a) {
    asm volatile("ldmatrix.sync.aligned.m8n8.x4.shared.b16 {%0,%1,%2,%3}, [%4];"
        : "=r"(r[0]), "=r"(r[1]), "=r"(r[2]), "=r"(r[3]) : "r"(a));
}
__device__ __forceinline__ void mma16816(float* c, const uint32_t* a, const uint32_t* b) {
    asm volatile("mma.sync.aligned.m16n8k16.row.col.f32.bf16.bf16.f32 "
        "{%0,%1,%2,%3}, {%4,%5,%6,%7}, {%8,%9}, {%0,%1,%2,%3};"
        : "+f"(c[0]), "+f"(c[1]), "+f"(c[2]), "+f"(c[3])
        : "r"(a[0]), "r"(a[1]), "r"(a[2]), "r"(a[3]), "r"(b[0]), "r"(b[1]));
}

// ---------------------------------------------------------------------------
__global__ void zero_kernel(float* q, float* h_out, float* pre, float* lpre) {
    int i = blockIdx.x * 256 + threadIdx.x;
    if (i < BB * FF) { q[i] = 0.f; h_out[i] = 0.f; }
    if (i < BB * SS) { pre[i] = 0.f; lpre[i] = 0.f; }
}

// split X (fp32 -> bf16 hi/lo), 1 float4 per thread
__global__ void splitX_kernel(const float4* __restrict__ X,
                              __nv_bfloat16* __restrict__ Xh,
                              __nv_bfloat16* __restrict__ Xl) {
    size_t i = (size_t)blockIdx.x * 256 + threadIdx.x;
    float4 v = X[i];
    __nv_bfloat16 h0,l0,h1,l1,h2,l2,h3,l3;
    split2(v.x,h0,l0); split2(v.y,h1,l1); split2(v.z,h2,l2); split2(v.w,h3,l3);
    __nv_bfloat162 *ph = (__nv_bfloat162*)Xh, *pl = (__nv_bfloat162*)Xl;
    __nv_bfloat162 a; a.x=h0; a.y=h1; ph[i*2] = a;
    a.x=h2; a.y=h3; ph[i*2+1] = a;
    a.x=l0; a.y=l1; pl[i*2]   = a;
    a.x=l2; a.y=l3; pl[i*2+1] = a;
}

// transpose + split weight: Th[n][k] = bf16hi(W[k][n]), Tl = residual
__global__ void transW_kernel(const float* __restrict__ W,
                              __nv_bfloat16* __restrict__ Th,
                              __nv_bfloat16* __restrict__ Tl) {
    __shared__ float t[32][33];
    int n0 = blockIdx.x * 32, k0 = blockIdx.y * 32;
    int x = threadIdx.x, y = threadIdx.y;   // 32x8
    #pragma unroll
    for (int d = 0; d < 32; d += 8)
        t[y + d][x] = W[(size_t)(k0 + y + d) * FF + n0 + x];
    __syncthreads();
    #pragma unroll
    for (int d = 0; d < 32; d += 8) {
        int n = n0 + y + d, k = k0 + x;
        __nv_bfloat16 h, l; split2(t[x][y + d], h, l);
        Th[(size_t)n * HH + k] = h;
        Tl[(size_t)n * HH + k] = l;
    }
}

// ---------------------------------------------------------------------------
// HMMA bf16x3 GEMM:  D[M,N] = A[M,K] @ B^T[N,K]   (fp32-equivalent)
// CTA tile 128x128x32, 8 warps (4M x 2N), warp tile 32x64, 3-stage cp.async.
// smem tile layout: 128 rows, 5 uint4 per row (4 data chunks, stride 80B).
// MODE 0: relu(acc+bias) -> bf16 hi/lo out
// MODE 1: relu(acc+bias) -> fp32 out + bf16 hi/lo out
// MODE 2: p = sum_n tanh(acc + t1[b,n] + bias[n]) * v[n]; atomicAdd(rowdot[m], p)
#define TILE_B 10240
#define BUF_B (4*TILE_B)
#define SMEM_GEMM (3*BUF_B)   // 122880

template <int MODE>
__global__ void __launch_bounds__(256, 1)
gemm_mma(const __nv_bfloat16* __restrict__ Ah_g, const __nv_bfloat16* __restrict__ Al_g,
         const __nv_bfloat16* __restrict__ Bh_g, const __nv_bfloat16* __restrict__ Bl_g,
         const float* __restrict__ bias,
         float* __restrict__ out_f32,
         __nv_bfloat16* __restrict__ out_h, __nv_bfloat16* __restrict__ out_l,
         const float* __restrict__ t1, const float* __restrict__ vvec,
         float* __restrict__ rowdot)
{
    extern __shared__ char smem[];
    uint32_t sb = (uint32_t)__cvta_generic_to_shared(smem);
    int tid = threadIdx.x, lane = tid & 31, wid = tid >> 5;
    int bn = blockIdx.x, bm = blockIdx.y;

    const __nv_bfloat16* srcs[4];
    srcs[0] = Ah_g + (size_t)bm * 128 * HH;
    srcs[1] = Al_g + (size_t)bm * 128 * HH;
    srcs[2] = Bh_g + (size_t)bn * 128 * HH;
    srcs[3] = Bl_g + (size_t)bn * 128 * HH;

    int ld_row = tid >> 2;          // e = tid + i*256: rows tid>>2 and 64+tid>>2
    int ld_ch  = tid & 3;

    // prologue: stages 0, 1
    #pragma unroll
    for (int c = 0; c < 2; c++) {
        uint32_t buf = sb + c * BUF_B;
        #pragma unroll
        for (int tI = 0; tI < 4; tI++) {
            const __nv_bfloat16* g = srcs[tI] + c * 32;
            #pragma unroll
            for (int i = 0; i < 2; i++) {
                int row = ld_row + i * 64;
                cpa16(buf + tI * TILE_B + row * 80 + ld_ch * 16,
                      g + (size_t)row * HH + ld_ch * 8);
            }
        }
        cp_commit();
    }

    float acc[2][8][4];
    #pragma unroll
    for (int mt = 0; mt < 2; mt++)
        #pragma unroll
        for (int nt = 0; nt < 8; nt++)
            #pragma unroll
            for (int e = 0; e < 4; e++) acc[mt][nt][e] = 0.f;

    int warpM = wid & 3, warpN = wid >> 2;
    int m0 = warpM * 32, n0 = warpN * 64;

    // precompute ldsm lane addresses (tile-relative)
    int a_row = (lane & 15);
    int a_chx = (lane >> 4);            // +0/+1 chunk
    int b_rowp = ((lane >> 4) << 3) + (lane & 7);
    int b_chx = ((lane >> 3) & 1);

    for (int c = 0; c < 32; c++) {
        if (c < 30) asm volatile("cp.async.wait_group 1;" ::: "memory");
        else        asm volatile("cp.async.wait_group 0;" ::: "memory");
        __syncthreads();

        if (c + 2 < 32) {
            uint32_t buf = sb + ((c + 2) % 3) * BUF_B;
            #pragma unroll
            for (int tI = 0; tI < 4; tI++) {
                const __nv_bfloat16* g = srcs[tI] + (c + 2) * 32;
                #pragma unroll
                for (int i = 0; i < 2; i++) {
                    int row = ld_row + i * 64;
                    cpa16(buf + tI * TILE_B + row * 80 + ld_ch * 16,
                          g + (size_t)row * HH + ld_ch * 8);
                }
            }
        }
        cp_commit();

        uint32_t buf = sb + (c % 3) * BUF_B;
        uint32_t As_h = buf, As_l = buf + TILE_B;
        uint32_t Bs_h = buf + 2 * TILE_B, Bs_l = buf + 3 * TILE_B;

        #pragma unroll
        for (int ks = 0; ks < 2; ks++) {
            uint32_t ah[2][4], al[2][4];
            #pragma unroll
            for (int mt = 0; mt < 2; mt++) {
                uint32_t off = (uint32_t)(m0 + mt * 16 + a_row) * 80
                             + (uint32_t)(ks * 2 + a_chx) * 16;
                ldsm4(ah[mt], As_h + off);
                ldsm4(al[mt], As_l + off);
            }
            uint32_t bh[8][2], bl[8][2];
            #pragma unroll
            for (int p = 0; p < 4; p++) {
                uint32_t off = (uint32_t)(n0 + p * 16 + b_rowp) * 80
                             + (uint32_t)(ks * 2 + b_chx) * 16;
                uint32_t r[4];
                ldsm4(r, Bs_h + off);
                bh[2*p][0] = r[0]; bh[2*p][1] = r[1];
                bh[2*p+1][0] = r[2]; bh[2*p+1][1] = r[3];
                ldsm4(r, Bs_l + off);
                bl[2*p][0] = r[0]; bl[2*p][1] = r[1];
                bl[2*p+1][0] = r[2]; bl[2*p+1][1] = r[3];
            }
            #pragma unroll
            for (int mt = 0; mt < 2; mt++)
                #pragma unroll
                for (int nt = 0; nt < 8; nt++) {
                    mma16816(acc[mt][nt], ah[mt], bh[nt]);
                    mma16816(acc[mt][nt], ah[mt], bl[nt]);
                    mma16816(acc[mt][nt], al[mt], bh[nt]);
                }
        }
    }

    // ---------------- epilogue ----------------
    int g4 = lane >> 2;           // row-in-8 group
    int cpair = (lane & 3) * 2;   // col pair base

    if (MODE == 2) {
        int batch = (bm * 128) >> 11;
        #pragma unroll
        for (int mt = 0; mt < 2; mt++) {
            #pragma unroll
            for (int h = 0; h < 2; h++) {
                int grow = bm * 128 + m0 + mt * 16 + g4 + h * 8;
                float p = 0.f;
                #pragma unroll
                for (int nt = 0; nt < 8; nt++) {
                    int n = bn * 128 + n0 + nt * 8 + cpair;
                    #pragma unroll
                    for (int e = 0; e < 2; e++) {
                        float x = acc[mt][nt][h * 2 + e] + t1[batch * FF + n + e] + bias[n + e];
                        p = fmaf(tanhf(x), vvec[n + e], p);
                    }
                }
                p += __shfl_xor_sync(0xffffffffu, p, 1);
                p += __shfl_xor_sync(0xffffffffu, p, 2);
                if ((lane & 3) == 0) atomicAdd(&rowdot[grow], p);
            }
        }
    } else {
        #pragma unroll
        for (int mt = 0; mt < 2; mt++) {
            #pragma unroll
            for (int h = 0; h < 2; h++) {
                int grow = bm * 128 + m0 + mt * 16 + g4 + h * 8;
                #pragma unroll
                for (int nt = 0; nt < 8; nt++) {
                    int n = bn * 128 + n0 + nt * 8 + cpair;
                    float v0 = acc[mt][nt][h * 2 + 0] + bias[n + 0];
                    float v1 = acc[mt][nt][h * 2 + 1] + bias[n + 1];
                    v0 = v0 > 0.f ? v0 : 0.f;
                    v1 = v1 > 0.f ? v1 : 0.f;
                    if (MODE == 1)
                        *(float2*)(out_f32 + (size_t)grow * FF + n) = make_float2(v0, v1);
                    __nv_bfloat16 h0, l0, h1, l1;
                    split2(v0, h0, l0); split2(v1, h1, l1);
                    uint32_t hp = (uint32_t)__bfloat16_as_ushort(h0) |
                                  ((uint32_t)__bfloat16_as_ushort(h1) << 16);
                    uint32_t lp = (uint32_t)__bfloat16_as_ushort(l0) |
                                  ((uint32_t)__bfloat16_as_ushort(l1) << 16);
                    *(uint32_t*)(out_h + (size_t)grow * FF + n) = hp;
                    *(uint32_t*)(out_l + (size_t)grow * FF + n) = lp;
                }
            }
        }
    }
}

// ---------------------------------------------------------------------------
// out[b,f] += sum_s (hi+lo)[b,s,f] * w[b,s]
__global__ void colreduce_bf(const __nv_bfloat16* __restrict__ Xh,
                             const __nv_bfloat16* __restrict__ Xl,
                             const float* __restrict__ w,
                             float* __restrict__ out)
{
    int f = blockIdx.x * 256 + threadIdx.x;
    int b = blockIdx.y;
    int s0 = blockIdx.z * 256;
    const __nv_bfloat16* hp = Xh + ((size_t)b * SS + s0) * FF + f;
    const __nv_bfloat16* lp = Xl + ((size_t)b * SS + s0) * FF + f;
    const float* wp = w + b * SS + s0;
    float acc = 0.f;
    #pragma unroll 4
    for (int s = 0; s < 256; s++) {
        float cv = __bfloat162float(hp[(size_t)s * FF]) + __bfloat162float(lp[(size_t)s * FF]);
        acc = fmaf(cv, wp[s], acc);
    }
    atomicAdd(&out[b * FF + f], acc);
}

// t1[b,n] = sum_k q[b,k] * w1[k,n]
__global__ void smallgemm_kernel(const float* __restrict__ q,
                                 const float* __restrict__ w1,
                                 float* __restrict__ t1)
{
    __shared__ float qs[256];
    int n = blockIdx.x * 256 + threadIdx.x;
    int b = blockIdx.y;
    float acc = 0.f;
    for (int k0 = 0; k0 < FF; k0 += 256) {
        __syncthreads();
        qs[threadIdx.x] = q[b * FF + k0 + threadIdx.x];
        __syncthreads();
        #pragma unroll 8
        for (int k = 0; k < 256; k++)
            acc = fmaf(qs[k], w1[(size_t)(k0 + k) * FF + n], acc);
    }
    t1[b * FF + n] = acc;
}

// ---------------------------------------------------------------------------
__device__ __forceinline__ float blockReduce(float v, bool do_max) {
    __shared__ float sm[32];
    __syncthreads();
    int lane = threadIdx.x & 31, wid = threadIdx.x >> 5;
    #pragma unroll
    for (int o = 16; o; o >>= 1) {
        float t = __shfl_down_sync(0xffffffffu, v, o);
        v = do_max ? fmaxf(v, t) : v + t;
    }
    if (lane == 0) sm[wid] = v;
    __syncthreads();
    int nw = blockDim.x >> 5;
    v = (threadIdx.x < nw) ? sm[threadIdx.x] : (do_max ? -1e30f : 0.f);
    if (wid == 0) {
        #pragma unroll
        for (int o = 16; o; o >>= 1) {
            float t = __shfl_down_sync(0xffffffffu, v, o);
            v = do_max ? fmaxf(v, t) : v + t;
        }
        if (lane == 0) sm[0] = v;
    }
    __syncthreads();
    return sm[0];
}

__global__ void softmax_kernel(const float* __restrict__ pre,
                               const float* __restrict__ mask,
                               float* __restrict__ alpha)
{
    int b = blockIdx.x, tid = threadIdx.x;
    float z[8];
    float mx = -1e30f;
    #pragma unroll
    for (int i = 0; i < 8; i++) {
        int s = tid + i * 256;
        z[i] = pre[b * SS + s] + (1.f - mask[b * SS + s]) * -10000.f;
        mx = fmaxf(mx, z[i]);
    }
    mx = blockReduce(mx, true);
    float sum = 0.f;
    #pragma unroll
    for (int i = 0; i < 8; i++) { z[i] = expf(z[i] - mx); sum += z[i]; }
    sum = blockReduce(sum, false);
    float inv = 1.f / sum;
    #pragma unroll
    for (int i = 0; i < 8; i++)
        alpha[b * SS + tid + i * 256] = z[i] * inv;
}

__global__ void sparsemax_kernel(const float* __restrict__ Lpre,
                                 const float* __restrict__ mask,
                                 const float* __restrict__ w_1,
                                 const float* __restrict__ w_2,
                                 const float* __restrict__ w_3,
                                 const int* __restrict__ layer_i,
                                 float* __restrict__ Lout)
{
    __shared__ float zs[SS];
    __shared__ float cum[SS];
    __shared__ int scnt;
    int b = blockIdx.x, tid = threadIdx.x;

    int li = layer_i[0];
    float a1 = w_1[0], a2 = w_2[0], a3 = w_3[0];
    float x;
    if (li == 0)      x = a3 * a3 - a2 * a2 - a1 * a1;
    else if (li == 1) x = a3 * a3 - a2 * a2;
    else              x = a3 * a3;
    float sig = 1.f / (1.f + expf(-x));

    for (int i = tid; i < SS; i += 1024)
        zs[i] = Lpre[b * SS + i] * sig + (1.f - mask[b * SS + i]) * -10000.f;
    if (tid == 0) scnt = 0;
    __syncthreads();

    for (int k = 2; k <= SS; k <<= 1) {
        for (int j = k >> 1; j > 0; j >>= 1) {
            for (int t = tid; t < SS; t += 1024) {
                int ixj = t ^ j;
                if (ixj > t) {
                    float a = zs[t], c = zs[ixj];
                    bool up = ((t & k) == 0);
                    if ((a > c) == up) { zs[t] = c; zs[ixj] = a; }
                }
            }
            __syncthreads();
        }
    }

    cum[tid]        = zs[SS - 1 - tid];
    cum[tid + 1024] = zs[SS - 1 - (tid + 1024)];
    __syncthreads();
    for (int off = 1; off < SS; off <<= 1) {
        float v0 = (tid >= off) ? cum[tid - off] : 0.f;
        float v1 = cum[tid + 1024 - off];
        __syncthreads();
        cum[tid] += v0;
        cum[tid + 1024] += v1;
        __syncthreads();
    }

    int c = 0;
    #pragma unroll
    for (int r = 0; r < 2; r++) {
        int i = tid + r * 1024;
        if (1.f + (float)(i + 1) * zs[SS - 1 - i] > cum[i]) c++;
    }
    atomicAdd(&scnt, c);
    __syncthreads();
    int ks = scnt;
    float tau = (cum[ks - 1] - 1.f) / (float)ks;

    for (int i = tid; i < SS; i += 1024) {
        float zv = Lpre[b * SS + i] * sig + (1.f - mask[b * SS + i]) * -10000.f;
        Lout[b * SS + i] = fmaxf(zv - tau, 0.f);
    }
}

// ---------------------------------------------------------------------------
extern "C" void kernel_launch(void* const* d_in, const int* in_sizes, int n_in,
                              void* d_out, int out_size)
{
    const float* mask      = (const float*)d_in[0];
    const float* X         = (const float*)d_in[1];
    const float* iw        = (const float*)d_in[2];
    const float* W_C       = (const float*)d_in[3];
    const float* b_C       = (const float*)d_in[4];
    const float* W_A       = (const float*)d_in[5];
    const float* b_A       = (const float*)d_in[6];
    const float* w1        = (const float*)d_in[7];
    const float* w2        = (const float*)d_in[8];
    const float* attn_bias = (const float*)d_in[9];
    const float* v         = (const float*)d_in[10];
    const float* w_1       = (const float*)d_in[11];
    const float* w_2s      = (const float*)d_in[12];
    const float* w_3       = (const float*)d_in[13];
    const int*   layer_i   = (const int*)d_in[14];

    float* out   = (float*)d_out;
    float* h_out = out;
    float* L_out = out + BB * FF;
    float* A_out = out + BB * FF + BB * SS;

    __nv_bfloat16 *pXh, *pXl, *pCh, *pCl, *pAh, *pAl;
    __nv_bfloat16 *pWCh, *pWCl, *pWAh, *pWAl, *pW2h, *pW2l;
    float *pq, *pt1, *ppre, *palpha, *pLpre;
    cudaGetSymbolAddress((void**)&pXh, g_Xh);   cudaGetSymbolAddress((void**)&pXl, g_Xl);
    cudaGetSymbolAddress((void**)&pCh, g_Ch);   cudaGetSymbolAddress((void**)&pCl, g_Cl);
    cudaGetSymbolAddress((void**)&pAh, g_Ahm);  cudaGetSymbolAddress((void**)&pAl, g_Alm);
    cudaGetSymbolAddress((void**)&pWCh, g_WCh); cudaGetSymbolAddress((void**)&pWCl, g_WCl);
    cudaGetSymbolAddress((void**)&pWAh, g_WAh); cudaGetSymbolAddress((void**)&pWAl, g_WAl);
    cudaGetSymbolAddress((void**)&pW2h, g_W2h); cudaGetSymbolAddress((void**)&pW2l, g_W2l);
    cudaGetSymbolAddress((void**)&pq, g_q);     cudaGetSymbolAddress((void**)&pt1, g_t1);
    cudaGetSymbolAddress((void**)&ppre, g_pre); cudaGetSymbolAddress((void**)&palpha, g_alpha);
    cudaGetSymbolAddress((void**)&pLpre, g_Lpre);

    cudaFuncSetAttribute(gemm_mma<0>, cudaFuncAttributeMaxDynamicSharedMemorySize, SMEM_GEMM);
    cudaFuncSetAttribute(gemm_mma<1>, cudaFuncAttributeMaxDynamicSharedMemorySize, SMEM_GEMM);
    cudaFuncSetAttribute(gemm_mma<2>, cudaFuncAttributeMaxDynamicSharedMemorySize, SMEM_GEMM);

    dim3 tgrid(FF / 128, MM / 128);   // (8, 256) — n fastest for A-tile L2 reuse
    dim3 wgrid(FF / 32, HH / 32);

    // 0) zero accumulators
    zero_kernel<<<128, 256>>>(pq, h_out, ppre, pLpre);
    // 1) prep: split X; transpose+split weights
    splitX_kernel<<<(MM * HH / 4) / 256, 256>>>((const float4*)X, pXh, pXl);
    transW_kernel<<<wgrid, dim3(32, 8)>>>(W_C, pWCh, pWCl);
    transW_kernel<<<wgrid, dim3(32, 8)>>>(W_A, pWAh, pWAl);
    transW_kernel<<<wgrid, dim3(32, 8)>>>(w2, pW2h, pW2l);
    // 2) C = relu(X@W_C + b_C) -> bf16 hi/lo
    gemm_mma<0><<<tgrid, 256, SMEM_GEMM>>>(pXh, pXl, pWCh, pWCl, b_C,
                                           nullptr, pCh, pCl, nullptr, nullptr, nullptr);
    // 3) A = relu(X@W_A + b_A) -> fp32 output + bf16 hi/lo
    gemm_mma<1><<<tgrid, 256, SMEM_GEMM>>>(pXh, pXl, pWAh, pWAl, b_A,
                                           A_out, pAh, pAl, nullptr, nullptr, nullptr);
    // 4) q = C^T @ item_weights
    colreduce_bf<<<dim3(FF / 256, BB, 8), 256>>>(pCh, pCl, iw, pq);
    // 5) t1 = q @ w1
    smallgemm_kernel<<<dim3(FF / 256, BB), 256>>>(pq, w1, pt1);
    // 6) alpha_pre = tanh(C@w2 + t1 + bias) . v
    gemm_mma<2><<<tgrid, 256, SMEM_GEMM>>>(pCh, pCl, pW2h, pW2l, attn_bias,
                                           nullptr, nullptr, nullptr, pt1, v, ppre);
    // 7) softmax
    softmax_kernel<<<BB, 256>>>(ppre, mask, palpha);
    // 8) h = C^T @ alpha
    colreduce_bf<<<dim3(FF / 256, BB, 8), 256>>>(pCh, pCl, palpha, h_out);
    // 9) t1 = h @ w1
    smallgemm_kernel<<<dim3(FF / 256, BB), 256>>>(h_out, w1, pt1);
    // 10) L_pre = tanh(A@w2 + t1 + bias) . v
    gemm_mma<2><<<tgrid, 256, SMEM_GEMM>>>(pAh, pAl, pW2h, pW2l, attn_bias,
                                           nullptr, nullptr, nullptr, pt1, v, pLpre);
    // 11) sparsemax
    sparsemax_kernel<<<BB, 1024>>>(pLpre, mask, w_1, w_2s, w_3, layer_i, L_out);
}

// round 4
// speedup vs baseline: 2.3999x; 1.1241x over previous
#include <cuda_runtime.h>
#include <cuda_bf16.h>
#include <math.h>
#include <stdint.h>

#define BB 16
#define SS 2048
#define HH 1024
#define FF 1024
#define MM (BB*SS)   // 32768

// ---------------- device scratch (no runtime allocation allowed) ----------
__device__ __nv_bfloat16 g_Xh[(size_t)MM*HH], g_Xl[(size_t)MM*HH];
__device__ __nv_bfloat16 g_Ch[(size_t)MM*FF], g_Cl[(size_t)MM*FF];
__device__ __nv_bfloat16 g_Ahm[(size_t)MM*FF], g_Alm[(size_t)MM*FF];
__device__ __nv_bfloat16 g_WCh[(size_t)FF*HH], g_WCl[(size_t)FF*HH];
__device__ __nv_bfloat16 g_WAh[(size_t)FF*HH], g_WAl[(size_t)FF*HH];
__device__ __nv_bfloat16 g_W2h[(size_t)FF*FF], g_W2l[(size_t)FF*FF];
__device__ float g_q[BB*FF];
__device__ float g_t1[BB*FF];
__device__ float g_pre[BB*SS];
__device__ float g_alpha[BB*SS];
__device__ float g_Lpre[BB*SS];

// ---------------------------------------------------------------------------
__device__ __forceinline__ void split2(float x, __nv_bfloat16& h, __nv_bfloat16& l) {
    h = __float2bfloat16(x);
    l = __float2bfloat16(x - __bfloat162float(h));
}

__device__ __forceinline__ void cpa16(uint32_t s, const void* g) {
    asm volatile("cp.async.cg.shared.global [%0], [%1], 16;" :: "r"(s), "l"(g));
}
__device__ __forceinline__ void cp_commit() {
    asm volatile("cp.async.commit_group;");
}
__device__ __forceinline__ void ldsm4(uint32_t* r, uint32_t a) {
    asm volatile("ldmatrix.sync.aligned.m8n8.x4.shared.b16 {%0,%1,%2,%3}, [%4];"
        : "=r"(r[0]), "=r"(r[1]), "=r"(r[2]), "=r"(r[3]) : "r"(a));
}
__device__ __forceinline__ void mma16816(float* c, const uint32_t* a, const uint32_t* b) {
    asm volatile("mma.sync.aligned.m16n8k16.row.col.f32.bf16.bf16.f32 "
        "{%0,%1,%2,%3}, {%4,%5,%6,%7}, {%8,%9}, {%0,%1,%2,%3};"
        : "+f"(c[0]), "+f"(c[1]), "+f"(c[2]), "+f"(c[3])
        : "r"(a[0]), "r"(a[1]), "r"(a[2]), "r"(a[3]), "r"(b[0]), "r"(b[1]));
}

// ---------------------------------------------------------------------------
__global__ void zero_kernel(float* q, float* h_out, float* pre, float* lpre) {
    int i = blockIdx.x * 256 + threadIdx.x;
    if (i < BB * FF) { q[i] = 0.f; h_out[i] = 0.f; }
    if (i < BB * SS) { pre[i] = 0.f; lpre[i] = 0.f; }
}

// split X (fp32 -> bf16 hi/lo), 1 float4 per thread
__global__ void splitX_kernel(const float4* __restrict__ X,
                              __nv_bfloat16* __restrict__ Xh,
                              __nv_bfloat16* __restrict__ Xl) {
    size_t i = (size_t)blockIdx.x * 256 + threadIdx.x;
    float4 v = X[i];
    __nv_bfloat16 h0,l0,h1,l1,h2,l2,h3,l3;
    split2(v.x,h0,l0); split2(v.y,h1,l1); split2(v.z,h2,l2); split2(v.w,h3,l3);
    __nv_bfloat162 *ph = (__nv_bfloat162*)Xh, *pl = (__nv_bfloat162*)Xl;
    __nv_bfloat162 a; a.x=h0; a.y=h1; ph[i*2] = a;
    a.x=h2; a.y=h3; ph[i*2+1] = a;
    a.x=l0; a.y=l1; pl[i*2]   = a;
    a.x=l2; a.y=l3; pl[i*2+1] = a;
}

// transpose + split weight: Th[n][k] = bf16hi(W[k][n]), Tl = residual
__global__ void transW_kernel(const float* __restrict__ W,
                              __nv_bfloat16* __restrict__ Th,
                              __nv_bfloat16* __restrict__ Tl) {
    __shared__ float t[32][33];
    int n0 = blockIdx.x * 32, k0 = blockIdx.y * 32;
    int x = threadIdx.x, y = threadIdx.y;   // 32x8
    #pragma unroll
    for (int d = 0; d < 32; d += 8)
        t[y + d][x] = W[(size_t)(k0 + y + d) * FF + n0 + x];
    __syncthreads();
    #pragma unroll
    for (int d = 0; d < 32; d += 8) {
        int n = n0 + y + d, k = k0 + x;
        __nv_bfloat16 h, l; split2(t[x][y + d], h, l);
        Th[(size_t)n * HH + k] = h;
        Tl[(size_t)n * HH + k] = l;
    }
}

// ---------------------------------------------------------------------------
// HMMA bf16x3 GEMM:  D[M,N] = A[M,K] @ B^T[N,K]   (fp32-equivalent)
// CTA tile 256x128x32, 8 warps (4M x 2N), warp tile 64x64, 3-stage cp.async.
// smem rows: stride 80B (64B data + 16B pad) -> conflict-free ldmatrix.
// MODE 0: relu(acc+bias) -> bf16 hi/lo out
// MODE 1: relu(acc+bias) -> fp32 out + bf16 hi/lo out
// MODE 2: p = sum_n tanh(acc + t1[b,n] + bias[n]) * v[n]; atomicAdd(rowdot[m], p)
#define KC 32
#define OFF_AH 0
#define OFF_AL 20480
#define OFF_BH 40960
#define OFF_BL 51200
#define STAGE_B 61440
#define SMEM_GEMM (3*STAGE_B)   // 184320

template <int MODE>
__global__ void __launch_bounds__(256, 1)
gemm_mma(const __nv_bfloat16* __restrict__ Ah_g, const __nv_bfloat16* __restrict__ Al_g,
         const __nv_bfloat16* __restrict__ Bh_g, const __nv_bfloat16* __restrict__ Bl_g,
         const float* __restrict__ bias,
         float* __restrict__ out_f32,
         __nv_bfloat16* __restrict__ out_h, __nv_bfloat16* __restrict__ out_l,
         const float* __restrict__ t1, const float* __restrict__ vvec,
         float* __restrict__ rowdot)
{
    extern __shared__ char smem[];
    uint32_t sb = (uint32_t)__cvta_generic_to_shared(smem);
    int tid = threadIdx.x, lane = tid & 31, wid = tid >> 5;
    int bn = blockIdx.x, bm = blockIdx.y;

    const __nv_bfloat16* srcs[4];
    srcs[0] = Ah_g + (size_t)bm * 256 * HH;
    srcs[1] = Al_g + (size_t)bm * 256 * HH;
    srcs[2] = Bh_g + (size_t)bn * 128 * HH;
    srcs[3] = Bl_g + (size_t)bn * 128 * HH;
    const uint32_t soff[4] = {OFF_AH, OFF_AL, OFF_BH, OFF_BL};

    int ld_row = tid >> 2;          // 0..63
    int ld_ch  = tid & 3;

    // prologue: stages 0, 1
    #pragma unroll
    for (int c = 0; c < 2; c++) {
        uint32_t buf = sb + c * STAGE_B;
        #pragma unroll
        for (int tI = 0; tI < 4; tI++) {
            const int nIt = (tI < 2) ? 4 : 2;
            const __nv_bfloat16* g = srcs[tI] + c * KC;
            #pragma unroll
            for (int i = 0; i < nIt; i++) {
                int row = ld_row + i * 64;
                cpa16(buf + soff[tI] + row * 80 + ld_ch * 16,
                      g + (size_t)row * HH + ld_ch * 8);
            }
        }
        cp_commit();
    }

    float acc[4][8][4];
    #pragma unroll
    for (int mt = 0; mt < 4; mt++)
        #pragma unroll
        for (int nt = 0; nt < 8; nt++)
            #pragma unroll
            for (int e = 0; e < 4; e++) acc[mt][nt][e] = 0.f;

    int warpM = wid & 3, warpN = wid >> 2;
    int m0 = warpM * 64, n0 = warpN * 64;

    uint32_t a_base = (uint32_t)(m0 + (lane & 15)) * 80 + (uint32_t)(lane >> 4) * 16;
    int b_rowp = ((lane >> 4) << 3) + (lane & 7);
    uint32_t b_base = (uint32_t)(n0 + b_rowp) * 80 + (uint32_t)((lane >> 3) & 1) * 16;

    for (int c = 0; c < 32; c++) {
        if (c < 30) asm volatile("cp.async.wait_group 1;" ::: "memory");
        else        asm volatile("cp.async.wait_group 0;" ::: "memory");
        __syncthreads();

        if (c + 2 < 32) {
            uint32_t buf = sb + ((c + 2) % 3) * STAGE_B;
            #pragma unroll
            for (int tI = 0; tI < 4; tI++) {
                const int nIt = (tI < 2) ? 4 : 2;
                const __nv_bfloat16* g = srcs[tI] + (c + 2) * KC;
                #pragma unroll
                for (int i = 0; i < nIt; i++) {
                    int row = ld_row + i * 64;
                    cpa16(buf + soff[tI] + row * 80 + ld_ch * 16,
                          g + (size_t)row * HH + ld_ch * 8);
                }
            }
        }
        cp_commit();

        uint32_t buf = sb + (c % 3) * STAGE_B;
        uint32_t AsH = buf + OFF_AH, AsL = buf + OFF_AL;
        uint32_t BsH = buf + OFF_BH, BsL = buf + OFF_BL;

        #pragma unroll
        for (int ks = 0; ks < 2; ks++) {
            uint32_t ah[4][4], al[4][4];
            #pragma unroll
            for (int mt = 0; mt < 4; mt++) {
                uint32_t off = a_base + (uint32_t)mt * 1280 + (uint32_t)ks * 32;
                ldsm4(ah[mt], AsH + off);
                ldsm4(al[mt], AsL + off);
            }
            uint32_t bh[8][2], bl[8][2];
            #pragma unroll
            for (int p = 0; p < 4; p++) {
                uint32_t off = b_base + (uint32_t)p * 1280 + (uint32_t)ks * 32;
                uint32_t r[4];
                ldsm4(r, BsH + off);
                bh[2*p][0] = r[0]; bh[2*p][1] = r[1];
                bh[2*p+1][0] = r[2]; bh[2*p+1][1] = r[3];
                ldsm4(r, BsL + off);
                bl[2*p][0] = r[0]; bl[2*p][1] = r[1];
                bl[2*p+1][0] = r[2]; bl[2*p+1][1] = r[3];
            }
            #pragma unroll
            for (int mt = 0; mt < 4; mt++)
                #pragma unroll
                for (int nt = 0; nt < 8; nt++) {
                    mma16816(acc[mt][nt], ah[mt], bh[nt]);
                    mma16816(acc[mt][nt], ah[mt], bl[nt]);
                    mma16816(acc[mt][nt], al[mt], bh[nt]);
                }
        }
    }

    // ---------------- epilogue ----------------
    int g4 = lane >> 2;           // row-in-8 group
    int cpair = (lane & 3) * 2;   // col pair base

    if (MODE == 2) {
        int batch = bm >> 3;      // 256 rows per bm; 2048 per batch
        #pragma unroll
        for (int mt = 0; mt < 4; mt++) {
            #pragma unroll
            for (int h = 0; h < 2; h++) {
                int grow = bm * 256 + m0 + mt * 16 + g4 + h * 8;
                float p = 0.f;
                #pragma unroll
                for (int nt = 0; nt < 8; nt++) {
                    int n = bn * 128 + n0 + nt * 8 + cpair;
                    #pragma unroll
                    for (int e = 0; e < 2; e++) {
                        float x = acc[mt][nt][h * 2 + e] + t1[batch * FF + n + e] + bias[n + e];
                        p = fmaf(tanhf(x), vvec[n + e], p);
                    }
                }
                p += __shfl_xor_sync(0xffffffffu, p, 1);
                p += __shfl_xor_sync(0xffffffffu, p, 2);
                if ((lane & 3) == 0) atomicAdd(&rowdot[grow], p);
            }
        }
    } else {
        #pragma unroll
        for (int mt = 0; mt < 4; mt++) {
            #pragma unroll
            for (int h = 0; h < 2; h++) {
                int grow = bm * 256 + m0 + mt * 16 + g4 + h * 8;
                #pragma unroll
                for (int nt = 0; nt < 8; nt++) {
                    int n = bn * 128 + n0 + nt * 8 + cpair;
                    float v0 = acc[mt][nt][h * 2 + 0] + bias[n + 0];
                    float v1 = acc[mt][nt][h * 2 + 1] + bias[n + 1];
                    v0 = v0 > 0.f ? v0 : 0.f;
                    v1 = v1 > 0.f ? v1 : 0.f;
                    if (MODE == 1)
                        *(float2*)(out_f32 + (size_t)grow * FF + n) = make_float2(v0, v1);
                    __nv_bfloat16 h0, l0, h1, l1;
                    split2(v0, h0, l0); split2(v1, h1, l1);
                    uint32_t hp = (uint32_t)__bfloat16_as_ushort(h0) |
                                  ((uint32_t)__bfloat16_as_ushort(h1) << 16);
                    uint32_t lp = (uint32_t)__bfloat16_as_ushort(l0) |
                                  ((uint32_t)__bfloat16_as_ushort(l1) << 16);
                    *(uint32_t*)(out_h + (size_t)grow * FF + n) = hp;
                    *(uint32_t*)(out_l + (size_t)grow * FF + n) = lp;
                }
            }
        }
    }
}

// ---------------------------------------------------------------------------
// out[b,f] += sum_s (hi+lo)[b,s,f] * w[b,s]
__global__ void colreduce_bf(const __nv_bfloat16* __restrict__ Xh,
                             const __nv_bfloat16* __restrict__ Xl,
                             const float* __restrict__ w,
                             float* __restrict__ out)
{
    int f = blockIdx.x * 256 + threadIdx.x;
    int b = blockIdx.y;
    int s0 = blockIdx.z * 256;
    const __nv_bfloat16* hp = Xh + ((size_t)b * SS + s0) * FF + f;
    const __nv_bfloat16* lp = Xl + ((size_t)b * SS + s0) * FF + f;
    const float* wp = w + b * SS + s0;
    float acc = 0.f;
    #pragma unroll 4
    for (int s = 0; s < 256; s++) {
        float cv = __bfloat162float(hp[(size_t)s * FF]) + __bfloat162float(lp[(size_t)s * FF]);
        acc = fmaf(cv, wp[s], acc);
    }
    atomicAdd(&out[b * FF + f], acc);
}

// t1[b,n] = sum_k q[b,k] * w1[k,n]
__global__ void smallgemm_kernel(const float* __restrict__ q,
                                 const float* __restrict__ w1,
                                 float* __restrict__ t1)
{
    __shared__ float qs[256];
    int n = blockIdx.x * 256 + threadIdx.x;
    int b = blockIdx.y;
    float acc = 0.f;
    for (int k0 = 0; k0 < FF; k0 += 256) {
        __syncthreads();
        qs[threadIdx.x] = q[b * FF + k0 + threadIdx.x];
        __syncthreads();
        #pragma unroll 8
        for (int k = 0; k < 256; k++)
            acc = fmaf(qs[k], w1[(size_t)(k0 + k) * FF + n], acc);
    }
    t1[b * FF + n] = acc;
}

// ---------------------------------------------------------------------------
__device__ __forceinline__ float blockReduce(float v, bool do_max) {
    __shared__ float sm[32];
    __syncthreads();
    int lane = threadIdx.x & 31, wid = threadIdx.x >> 5;
    #pragma unroll
    for (int o = 16; o; o >>= 1) {
        float t = __shfl_down_sync(0xffffffffu, v, o);
        v = do_max ? fmaxf(v, t) : v + t;
    }
    if (lane == 0) sm[wid] = v;
    __syncthreads();
    int nw = blockDim.x >> 5;
    v = (threadIdx.x < nw) ? sm[threadIdx.x] : (do_max ? -1e30f : 0.f);
    if (wid == 0) {
        #pragma unroll
        for (int o = 16; o; o >>= 1) {
            float t = __shfl_down_sync(0xffffffffu, v, o);
            v = do_max ? fmaxf(v, t) : v + t;
        }
        if (lane == 0) sm[0] = v;
    }
    __syncthreads();
    return sm[0];
}

__global__ void softmax_kernel(const float* __restrict__ pre,
                               const float* __restrict__ mask,
                               float* __restrict__ alpha)
{
    int b = blockIdx.x, tid = threadIdx.x;
    float z[8];
    float mx = -1e30f;
    #pragma unroll
    for (int i = 0; i < 8; i++) {
        int s = tid + i * 256;
        z[i] = pre[b * SS + s] + (1.f - mask[b * SS + s]) * -10000.f;
        mx = fmaxf(mx, z[i]);
    }
    mx = blockReduce(mx, true);
    float sum = 0.f;
    #pragma unroll
    for (int i = 0; i < 8; i++) { z[i] = expf(z[i] - mx); sum += z[i]; }
    sum = blockReduce(sum, false);
    float inv = 1.f / sum;
    #pragma unroll
    for (int i = 0; i < 8; i++)
        alpha[b * SS + tid + i * 256] = z[i] * inv;
}

__global__ void sparsemax_kernel(const float* __restrict__ Lpre,
                                 const float* __restrict__ mask,
                                 const float* __restrict__ w_1,
                                 const float* __restrict__ w_2,
                                 const float* __restrict__ w_3,
                                 const int* __restrict__ layer_i,
                                 float* __restrict__ Lout)
{
    __shared__ float zs[SS];
    __shared__ float cum[SS];
    __shared__ int scnt;
    int b = blockIdx.x, tid = threadIdx.x;

    int li = layer_i[0];
    float a1 = w_1[0], a2 = w_2[0], a3 = w_3[0];
    float x;
    if (li == 0)      x = a3 * a3 - a2 * a2 - a1 * a1;
    else if (li == 1) x = a3 * a3 - a2 * a2;
    else              x = a3 * a3;
    float sig = 1.f / (1.f + expf(-x));

    for (int i = tid; i < SS; i += 1024)
        zs[i] = Lpre[b * SS + i] * sig + (1.f - mask[b * SS + i]) * -10000.f;
    if (tid == 0) scnt = 0;
    __syncthreads();

    for (int k = 2; k <= SS; k <<= 1) {
        for (int j = k >> 1; j > 0; j >>= 1) {
            for (int t = tid; t < SS; t += 1024) {
                int ixj = t ^ j;
                if (ixj > t) {
                    float a = zs[t], c = zs[ixj];
                    bool up = ((t & k) == 0);
                    if ((a > c) == up) { zs[t] = c; zs[ixj] = a; }
                }
            }
            __syncthreads();
        }
    }

    cum[tid]        = zs[SS - 1 - tid];
    cum[tid + 1024] = zs[SS - 1 - (tid + 1024)];
    __syncthreads();
    for (int off = 1; off < SS; off <<= 1) {
        float v0 = (tid >= off) ? cum[tid - off] : 0.f;
        float v1 = cum[tid + 1024 - off];
        __syncthreads();
        cum[tid] += v0;
        cum[tid + 1024] += v1;
        __syncthreads();
    }

    int c = 0;
    #pragma unroll
    for (int r = 0; r < 2; r++) {
        int i = tid + r * 1024;
        if (1.f + (float)(i + 1) * zs[SS - 1 - i] > cum[i]) c++;
    }
    atomicAdd(&scnt, c);
    __syncthreads();
    int ks = scnt;
    float tau = (cum[ks - 1] - 1.f) / (float)ks;

    for (int i = tid; i < SS; i += 1024) {
        float zv = Lpre[b * SS + i] * sig + (1.f - mask[b * SS + i]) * -10000.f;
        Lout[b * SS + i] = fmaxf(zv - tau, 0.f);
    }
}

// ---------------------------------------------------------------------------
extern "C" void kernel_launch(void* const* d_in, const int* in_sizes, int n_in,
                              void* d_out, int out_size)
{
    const float* mask      = (const float*)d_in[0];
    const float* X         = (const float*)d_in[1];
    const float* iw        = (const float*)d_in[2];
    const float* W_C       = (const float*)d_in[3];
    const float* b_C       = (const float*)d_in[4];
    const float* W_A       = (const float*)d_in[5];
    const float* b_A       = (const float*)d_in[6];
    const float* w1        = (const float*)d_in[7];
    const float* w2        = (const float*)d_in[8];
    const float* attn_bias = (const float*)d_in[9];
    const float* v         = (const float*)d_in[10];
    const float* w_1       = (const float*)d_in[11];
    const float* w_2s      = (const float*)d_in[12];
    const float* w_3       = (const float*)d_in[13];
    const int*   layer_i   = (const int*)d_in[14];

    float* out   = (float*)d_out;
    float* h_out = out;
    float* L_out = out + BB * FF;
    float* A_out = out + BB * FF + BB * SS;

    __nv_bfloat16 *pXh, *pXl, *pCh, *pCl, *pAh, *pAl;
    __nv_bfloat16 *pWCh, *pWCl, *pWAh, *pWAl, *pW2h, *pW2l;
    float *pq, *pt1, *ppre, *palpha, *pLpre;
    cudaGetSymbolAddress((void**)&pXh, g_Xh);   cudaGetSymbolAddress((void**)&pXl, g_Xl);
    cudaGetSymbolAddress((void**)&pCh, g_Ch);   cudaGetSymbolAddress((void**)&pCl, g_Cl);
    cudaGetSymbolAddress((void**)&pAh, g_Ahm);  cudaGetSymbolAddress((void**)&pAl, g_Alm);
    cudaGetSymbolAddress((void**)&pWCh, g_WCh); cudaGetSymbolAddress((void**)&pWCl, g_WCl);
    cudaGetSymbolAddress((void**)&pWAh, g_WAh); cudaGetSymbolAddress((void**)&pWAl, g_WAl);
    cudaGetSymbolAddress((void**)&pW2h, g_W2h); cudaGetSymbolAddress((void**)&pW2l, g_W2l);
    cudaGetSymbolAddress((void**)&pq, g_q);     cudaGetSymbolAddress((void**)&pt1, g_t1);
    cudaGetSymbolAddress((void**)&ppre, g_pre); cudaGetSymbolAddress((void**)&palpha, g_alpha);
    cudaGetSymbolAddress((void**)&pLpre, g_Lpre);

    cudaFuncSetAttribute(gemm_mma<0>, cudaFuncAttributeMaxDynamicSharedMemorySize, SMEM_GEMM);
    cudaFuncSetAttribute(gemm_mma<1>, cudaFuncAttributeMaxDynamicSharedMemorySize, SMEM_GEMM);
    cudaFuncSetAttribute(gemm_mma<2>, cudaFuncAttributeMaxDynamicSharedMemorySize, SMEM_GEMM);

    dim3 tgrid(FF / 128, MM / 256);   // (8, 128) — n fastest for A-tile L2 reuse
    dim3 wgrid(FF / 32, HH / 32);

    // 0) zero accumulators
    zero_kernel<<<128, 256>>>(pq, h_out, ppre, pLpre);
    // 1) prep: split X; transpose+split weights
    splitX_kernel<<<(MM * HH / 4) / 256, 256>>>((const float4*)X, pXh, pXl);
    transW_kernel<<<wgrid, dim3(32, 8)>>>(W_C, pWCh, pWCl);
    transW_kernel<<<wgrid, dim3(32, 8)>>>(W_A, pWAh, pWAl);
    transW_kernel<<<wgrid, dim3(32, 8)>>>(w2, pW2h, pW2l);
    // 2) C = relu(X@W_C + b_C) -> bf16 hi/lo
    gemm_mma<0><<<tgrid, 256, SMEM_GEMM>>>(pXh, pXl, pWCh, pWCl, b_C,
                                           nullptr, pCh, pCl, nullptr, nullptr, nullptr);
    // 3) A = relu(X@W_A + b_A) -> fp32 output + bf16 hi/lo
    gemm_mma<1><<<tgrid, 256, SMEM_GEMM>>>(pXh, pXl, pWAh, pWAl, b_A,
                                           A_out, pAh, pAl, nullptr, nullptr, nullptr);
    // 4) q = C^T @ item_weights
    colreduce_bf<<<dim3(FF / 256, BB, 8), 256>>>(pCh, pCl, iw, pq);
    // 5) t1 = q @ w1
    smallgemm_kernel<<<dim3(FF / 256, BB), 256>>>(pq, w1, pt1);
    // 6) alpha_pre = tanh(C@w2 + t1 + bias) . v
    gemm_mma<2><<<tgrid, 256, SMEM_GEMM>>>(pCh, pCl, pW2h, pW2l, attn_bias,
                                           nullptr, nullptr, nullptr, pt1, v, ppre);
    // 7) softmax
    softmax_kernel<<<BB, 256>>>(ppre, mask, palpha);
    // 8) h = C^T @ alpha
    colreduce_bf<<<dim3(FF / 256, BB, 8), 256>>>(pCh, pCl, palpha, h_out);
    // 9) t1 = h @ w1
    smallgemm_kernel<<<dim3(FF / 256, BB), 256>>>(h_out, w1, pt1);
    // 10) L_pre = tanh(A@w2 + t1 + bias) . v
    gemm_mma<2><<<tgrid, 256, SMEM_GEMM>>>(pAh, pAl, pW2h, pW2l, attn_bias,
                                           nullptr, nullptr, nullptr, pt1, v, pLpre);
    // 11) sparsemax
    sparsemax_kernel<<<BB, 1024>>>(pLpre, mask, w_1, w_2s, w_3, layer_i, L_out);
}

// round 5
// speedup vs baseline: 4.9684x; 2.0702x over previous
#include <cuda_runtime.h>
#include <cuda_fp16.h>
#include <math.h>
#include <stdint.h>

#define BB 16
#define SS 2048
#define HH 1024
#define FF 1024
#define MM (BB*SS)   // 32768

// ---------------- device scratch (no runtime allocation allowed) ----------
__device__ __half g_Xh[(size_t)MM*HH];
__device__ __half g_Ch[(size_t)MM*FF];
__device__ __half g_Am[(size_t)MM*FF];
__device__ __half g_WCh[(size_t)FF*HH];
__device__ __half g_WAh[(size_t)FF*HH];
__device__ __half g_W2h[(size_t)FF*FF];
__device__ float g_q[BB*FF];
__device__ float g_t1[BB*FF];
__device__ float g_pre[BB*SS];
__device__ float g_alpha[BB*SS];
__device__ float g_Lpre[BB*SS];

// ---------------------------------------------------------------------------
__device__ __forceinline__ void cpa16(uint32_t s, const void* g) {
    asm volatile("cp.async.cg.shared.global [%0], [%1], 16;" :: "r"(s), "l"(g));
}
__device__ __forceinline__ void cp_commit() {
    asm volatile("cp.async.commit_group;");
}
__device__ __forceinline__ void ldsm4(uint32_t* r, uint32_t a) {
    asm volatile("ldmatrix.sync.aligned.m8n8.x4.shared.b16 {%0,%1,%2,%3}, [%4];"
        : "=r"(r[0]), "=r"(r[1]), "=r"(r[2]), "=r"(r[3]) : "r"(a));
}
__device__ __forceinline__ void mma16816(float* c, const uint32_t* a, const uint32_t* b) {
    asm volatile("mma.sync.aligned.m16n8k16.row.col.f32.f16.f16.f32 "
        "{%0,%1,%2,%3}, {%4,%5,%6,%7}, {%8,%9}, {%0,%1,%2,%3};"
        : "+f"(c[0]), "+f"(c[1]), "+f"(c[2]), "+f"(c[3])
        : "r"(a[0]), "r"(a[1]), "r"(a[2]), "r"(a[3]), "r"(b[0]), "r"(b[1]));
}

// ---------------------------------------------------------------------------
__global__ void zero_kernel(float* q, float* h_out, float* pre, float* lpre) {
    int i = blockIdx.x * 256 + threadIdx.x;
    if (i < BB * FF) { q[i] = 0.f; h_out[i] = 0.f; }
    if (i < BB * SS) { pre[i] = 0.f; lpre[i] = 0.f; }
}

// convert X fp32 -> fp16, 1 float4 per thread
__global__ void cvtX_kernel(const float4* __restrict__ X, __half* __restrict__ Xh) {
    size_t i = (size_t)blockIdx.x * 256 + threadIdx.x;
    float4 v = X[i];
    __half2* p = (__half2*)Xh;
    p[i*2]   = __floats2half2_rn(v.x, v.y);
    p[i*2+1] = __floats2half2_rn(v.z, v.w);
}

// transpose + convert weight: T[n][k] = fp16(W[k][n])
__global__ void transW_kernel(const float* __restrict__ W, __half* __restrict__ T) {
    __shared__ float t[32][33];
    int n0 = blockIdx.x * 32, k0 = blockIdx.y * 32;
    int x = threadIdx.x, y = threadIdx.y;   // 32x8
    #pragma unroll
    for (int d = 0; d < 32; d += 8)
        t[y + d][x] = W[(size_t)(k0 + y + d) * FF + n0 + x];
    __syncthreads();
    #pragma unroll
    for (int d = 0; d < 32; d += 8) {
        int n = n0 + y + d, k = k0 + x;
        T[(size_t)n * HH + k] = __float2half(t[x][y + d]);
    }
}

// ---------------------------------------------------------------------------
// HMMA fp16 GEMM:  D[M,N] = A[M,K] @ B^T[N,K]
// CTA tile 256x128x32, 8 warps (4M x 2N), warp tile 64x64, 4-stage cp.async.
// smem rows: stride 80B (64B data + 16B pad) -> conflict-free ldmatrix.
// MODE 0: relu(acc+bias) -> fp16 out
// MODE 1: relu(acc+bias) -> fp32 out + fp16 out
// MODE 2: p = sum_n tanh(acc + t1[b,n] + bias[n]) * v[n]; atomicAdd(rowdot[m], p)
#define KC 32
#define OFF_A 0
#define OFF_B 20480
#define STAGE_B 30720
#define NSTAGE 4
#define SMEM_GEMM (NSTAGE*STAGE_B)   // 122880

template <int MODE>
__global__ void __launch_bounds__(256, 1)
gemm_mma(const __half* __restrict__ A_g, const __half* __restrict__ B_g,
         const float* __restrict__ bias,
         float* __restrict__ out_f32, __half* __restrict__ out_h,
         const float* __restrict__ t1, const float* __restrict__ vvec,
         float* __restrict__ rowdot)
{
    extern __shared__ char smem[];
    uint32_t sb = (uint32_t)__cvta_generic_to_shared(smem);
    int tid = threadIdx.x, lane = tid & 31, wid = tid >> 5;
    int bn = blockIdx.x, bm = blockIdx.y;

    const __half* Asrc = A_g + (size_t)bm * 256 * HH;
    const __half* Bsrc = B_g + (size_t)bn * 128 * HH;

    int ld_row = tid >> 2;          // 0..63
    int ld_ch  = tid & 3;

    // prologue: stages 0..2
    #pragma unroll
    for (int c = 0; c < NSTAGE - 1; c++) {
        uint32_t buf = sb + c * STAGE_B;
        #pragma unroll
        for (int i = 0; i < 4; i++) {
            int row = ld_row + i * 64;
            cpa16(buf + OFF_A + row * 80 + ld_ch * 16,
                  Asrc + (size_t)row * HH + c * KC + ld_ch * 8);
        }
        #pragma unroll
        for (int i = 0; i < 2; i++) {
            int row = ld_row + i * 64;
            cpa16(buf + OFF_B + row * 80 + ld_ch * 16,
                  Bsrc + (size_t)row * HH + c * KC + ld_ch * 8);
        }
        cp_commit();
    }

    float acc[4][8][4];
    #pragma unroll
    for (int mt = 0; mt < 4; mt++)
        #pragma unroll
        for (int nt = 0; nt < 8; nt++)
            #pragma unroll
            for (int e = 0; e < 4; e++) acc[mt][nt][e] = 0.f;

    int warpM = wid & 3, warpN = wid >> 2;
    int m0 = warpM * 64, n0 = warpN * 64;

    uint32_t a_base = (uint32_t)(m0 + (lane & 15)) * 80 + (uint32_t)(lane >> 4) * 16;
    int b_rowp = ((lane >> 4) << 3) + (lane & 7);
    uint32_t b_base = (uint32_t)(n0 + b_rowp) * 80 + (uint32_t)((lane >> 3) & 1) * 16;

    for (int c = 0; c < 32; c++) {
        if (c < 29) asm volatile("cp.async.wait_group 2;" ::: "memory");
        else        asm volatile("cp.async.wait_group 0;" ::: "memory");
        __syncthreads();

        if (c + NSTAGE - 1 < 32) {
            uint32_t buf = sb + ((c + NSTAGE - 1) % NSTAGE) * STAGE_B;
            int kc0 = (c + NSTAGE - 1) * KC;
            #pragma unroll
            for (int i = 0; i < 4; i++) {
                int row = ld_row + i * 64;
                cpa16(buf + OFF_A + row * 80 + ld_ch * 16,
                      Asrc + (size_t)row * HH + kc0 + ld_ch * 8);
            }
            #pragma unroll
            for (int i = 0; i < 2; i++) {
                int row = ld_row + i * 64;
                cpa16(buf + OFF_B + row * 80 + ld_ch * 16,
                      Bsrc + (size_t)row * HH + kc0 + ld_ch * 8);
            }
        }
        cp_commit();

        uint32_t buf = sb + (c % NSTAGE) * STAGE_B;
        uint32_t As = buf + OFF_A, Bs = buf + OFF_B;

        #pragma unroll
        for (int ks = 0; ks < 2; ks++) {
            uint32_t ah[4][4];
            #pragma unroll
            for (int mt = 0; mt < 4; mt++)
                ldsm4(ah[mt], As + a_base + (uint32_t)mt * 1280 + (uint32_t)ks * 32);
            uint32_t bh[8][2];
            #pragma unroll
            for (int p = 0; p < 4; p++) {
                uint32_t r[4];
                ldsm4(r, Bs + b_base + (uint32_t)p * 1280 + (uint32_t)ks * 32);
                bh[2*p][0] = r[0]; bh[2*p][1] = r[1];
                bh[2*p+1][0] = r[2]; bh[2*p+1][1] = r[3];
            }
            #pragma unroll
            for (int mt = 0; mt < 4; mt++)
                #pragma unroll
                for (int nt = 0; nt < 8; nt++)
                    mma16816(acc[mt][nt], ah[mt], bh[nt]);
        }
    }

    // ---------------- epilogue ----------------
    int g4 = lane >> 2;           // row-in-8 group
    int cpair = (lane & 3) * 2;   // col pair base

    if (MODE == 2) {
        int batch = bm >> 3;      // 256 rows per bm; 2048 per batch
        #pragma unroll
        for (int mt = 0; mt < 4; mt++) {
            #pragma unroll
            for (int h = 0; h < 2; h++) {
                int grow = bm * 256 + m0 + mt * 16 + g4 + h * 8;
                float p = 0.f;
                #pragma unroll
                for (int nt = 0; nt < 8; nt++) {
                    int n = bn * 128 + n0 + nt * 8 + cpair;
                    #pragma unroll
                    for (int e = 0; e < 2; e++) {
                        float x = acc[mt][nt][h * 2 + e] + t1[batch * FF + n + e] + bias[n + e];
                        p = fmaf(tanhf(x), vvec[n + e], p);
                    }
                }
                p += __shfl_xor_sync(0xffffffffu, p, 1);
                p += __shfl_xor_sync(0xffffffffu, p, 2);
                if ((lane & 3) == 0) atomicAdd(&rowdot[grow], p);
            }
        }
    } else {
        #pragma unroll
        for (int mt = 0; mt < 4; mt++) {
            #pragma unroll
            for (int h = 0; h < 2; h++) {
                int grow = bm * 256 + m0 + mt * 16 + g4 + h * 8;
                #pragma unroll
                for (int nt = 0; nt < 8; nt++) {
                    int n = bn * 128 + n0 + nt * 8 + cpair;
                    float v0 = acc[mt][nt][h * 2 + 0] + bias[n + 0];
                    float v1 = acc[mt][nt][h * 2 + 1] + bias[n + 1];
                    v0 = v0 > 0.f ? v0 : 0.f;
                    v1 = v1 > 0.f ? v1 : 0.f;
                    if (MODE == 1)
                        *(float2*)(out_f32 + (size_t)grow * FF + n) = make_float2(v0, v1);
                    *(__half2*)(out_h + (size_t)grow * FF + n) = __floats2half2_rn(v0, v1);
                }
            }
        }
    }
}

// ---------------------------------------------------------------------------
// out[b,f] += sum_s X[b,s,f] * w[b,s]
__global__ void colreduce_h(const __half* __restrict__ Xh,
                            const float* __restrict__ w,
                            float* __restrict__ out)
{
    int f = blockIdx.x * 256 + threadIdx.x;
    int b = blockIdx.y;
    int s0 = blockIdx.z * 256;
    const __half* hp = Xh + ((size_t)b * SS + s0) * FF + f;
    const float* wp = w + b * SS + s0;
    float acc = 0.f;
    #pragma unroll 4
    for (int s = 0; s < 256; s++)
        acc = fmaf(__half2float(hp[(size_t)s * FF]), wp[s], acc);
    atomicAdd(&out[b * FF + f], acc);
}

// t1[b,n] = sum_k q[b,k] * w1[k,n]
__global__ void smallgemm_kernel(const float* __restrict__ q,
                                 const float* __restrict__ w1,
                                 float* __restrict__ t1)
{
    __shared__ float qs[256];
    int n = blockIdx.x * 256 + threadIdx.x;
    int b = blockIdx.y;
    float acc = 0.f;
    for (int k0 = 0; k0 < FF; k0 += 256) {
        __syncthreads();
        qs[threadIdx.x] = q[b * FF + k0 + threadIdx.x];
        __syncthreads();
        #pragma unroll 8
        for (int k = 0; k < 256; k++)
            acc = fmaf(qs[k], w1[(size_t)(k0 + k) * FF + n], acc);
    }
    t1[b * FF + n] = acc;
}

// ---------------------------------------------------------------------------
__device__ __forceinline__ float blockReduce(float v, bool do_max) {
    __shared__ float sm[32];
    __syncthreads();
    int lane = threadIdx.x & 31, wid = threadIdx.x >> 5;
    #pragma unroll
    for (int o = 16; o; o >>= 1) {
        float t = __shfl_down_sync(0xffffffffu, v, o);
        v = do_max ? fmaxf(v, t) : v + t;
    }
    if (lane == 0) sm[wid] = v;
    __syncthreads();
    int nw = blockDim.x >> 5;
    v = (threadIdx.x < nw) ? sm[threadIdx.x] : (do_max ? -1e30f : 0.f);
    if (wid == 0) {
        #pragma unroll
        for (int o = 16; o; o >>= 1) {
            float t = __shfl_down_sync(0xffffffffu, v, o);
            v = do_max ? fmaxf(v, t) : v + t;
        }
        if (lane == 0) sm[0] = v;
    }
    __syncthreads();
    return sm[0];
}

__global__ void softmax_kernel(const float* __restrict__ pre,
                               const float* __restrict__ mask,
                               float* __restrict__ alpha)
{
    int b = blockIdx.x, tid = threadIdx.x;
    float z[8];
    float mx = -1e30f;
    #pragma unroll
    for (int i = 0; i < 8; i++) {
        int s = tid + i * 256;
        z[i] = pre[b * SS + s] + (1.f - mask[b * SS + s]) * -10000.f;
        mx = fmaxf(mx, z[i]);
    }
    mx = blockReduce(mx, true);
    float sum = 0.f;
    #pragma unroll
    for (int i = 0; i < 8; i++) { z[i] = expf(z[i] - mx); sum += z[i]; }
    sum = blockReduce(sum, false);
    float inv = 1.f / sum;
    #pragma unroll
    for (int i = 0; i < 8; i++)
        alpha[b * SS + tid + i * 256] = z[i] * inv;
}

__global__ void sparsemax_kernel(const float* __restrict__ Lpre,
                                 const float* __restrict__ mask,
                                 const float* __restrict__ w_1,
                                 const float* __restrict__ w_2,
                                 const float* __restrict__ w_3,
                                 const int* __restrict__ layer_i,
                                 float* __restrict__ Lout)
{
    __shared__ float zs[SS];
    __shared__ float cum[SS];
    __shared__ int scnt;
    int b = blockIdx.x, tid = threadIdx.x;

    int li = layer_i[0];
    float a1 = w_1[0], a2 = w_2[0], a3 = w_3[0];
    float x;
    if (li == 0)      x = a3 * a3 - a2 * a2 - a1 * a1;
    else if (li == 1) x = a3 * a3 - a2 * a2;
    else              x = a3 * a3;
    float sig = 1.f / (1.f + expf(-x));

    for (int i = tid; i < SS; i += 1024)
        zs[i] = Lpre[b * SS + i] * sig + (1.f - mask[b * SS + i]) * -10000.f;
    if (tid == 0) scnt = 0;
    __syncthreads();

    for (int k = 2; k <= SS; k <<= 1) {
        for (int j = k >> 1; j > 0; j >>= 1) {
            for (int t = tid; t < SS; t += 1024) {
                int ixj = t ^ j;
                if (ixj > t) {
                    float a = zs[t], c = zs[ixj];
                    bool up = ((t & k) == 0);
                    if ((a > c) == up) { zs[t] = c; zs[ixj] = a; }
                }
            }
            __syncthreads();
        }
    }

    cum[tid]        = zs[SS - 1 - tid];
    cum[tid + 1024] = zs[SS - 1 - (tid + 1024)];
    __syncthreads();
    for (int off = 1; off < SS; off <<= 1) {
        float v0 = (tid >= off) ? cum[tid - off] : 0.f;
        float v1 = cum[tid + 1024 - off];
        __syncthreads();
        cum[tid] += v0;
        cum[tid + 1024] += v1;
        __syncthreads();
    }

    int c = 0;
    #pragma unroll
    for (int r = 0; r < 2; r++) {
        int i = tid + r * 1024;
        if (1.f + (float)(i + 1) * zs[SS - 1 - i] > cum[i]) c++;
    }
    atomicAdd(&scnt, c);
    __syncthreads();
    int ks = scnt;
    float tau = (cum[ks - 1] - 1.f) / (float)ks;

    for (int i = tid; i < SS; i += 1024) {
        float zv = Lpre[b * SS + i] * sig + (1.f - mask[b * SS + i]) * -10000.f;
        Lout[b * SS + i] = fmaxf(zv - tau, 0.f);
    }
}

// ---------------------------------------------------------------------------
extern "C" void kernel_launch(void* const* d_in, const int* in_sizes, int n_in,
                              void* d_out, int out_size)
{
    const float* mask      = (const float*)d_in[0];
    const float* X         = (const float*)d_in[1];
    const float* iw        = (const float*)d_in[2];
    const float* W_C       = (const float*)d_in[3];
    const float* b_C       = (const float*)d_in[4];
    const float* W_A       = (const float*)d_in[5];
    const float* b_A       = (const float*)d_in[6];
    const float* w1        = (const float*)d_in[7];
    const float* w2        = (const float*)d_in[8];
    const float* attn_bias = (const float*)d_in[9];
    const float* v         = (const float*)d_in[10];
    const float* w_1       = (const float*)d_in[11];
    const float* w_2s      = (const float*)d_in[12];
    const float* w_3       = (const float*)d_in[13];
    const int*   layer_i   = (const int*)d_in[14];

    float* out   = (float*)d_out;
    float* h_out = out;
    float* L_out = out + BB * FF;
    float* A_out = out + BB * FF + BB * SS;

    __half *pXh, *pCh, *pAh, *pWCh, *pWAh, *pW2h;
    float *pq, *pt1, *ppre, *palpha, *pLpre;
    cudaGetSymbolAddress((void**)&pXh, g_Xh);
    cudaGetSymbolAddress((void**)&pCh, g_Ch);
    cudaGetSymbolAddress((void**)&pAh, g_Am);
    cudaGetSymbolAddress((void**)&pWCh, g_WCh);
    cudaGetSymbolAddress((void**)&pWAh, g_WAh);
    cudaGetSymbolAddress((void**)&pW2h, g_W2h);
    cudaGetSymbolAddress((void**)&pq, g_q);
    cudaGetSymbolAddress((void**)&pt1, g_t1);
    cudaGetSymbolAddress((void**)&ppre, g_pre);
    cudaGetSymbolAddress((void**)&palpha, g_alpha);
    cudaGetSymbolAddress((void**)&pLpre, g_Lpre);

    cudaFuncSetAttribute(gemm_mma<0>, cudaFuncAttributeMaxDynamicSharedMemorySize, SMEM_GEMM);
    cudaFuncSetAttribute(gemm_mma<1>, cudaFuncAttributeMaxDynamicSharedMemorySize, SMEM_GEMM);
    cudaFuncSetAttribute(gemm_mma<2>, cudaFuncAttributeMaxDynamicSharedMemorySize, SMEM_GEMM);

    dim3 tgrid(FF / 128, MM / 256);   // (8, 128) — n fastest for A-tile L2 reuse
    dim3 wgrid(FF / 32, HH / 32);

    // 0) zero accumulators
    zero_kernel<<<128, 256>>>(pq, h_out, ppre, pLpre);
    // 1) prep: convert X; transpose+convert weights
    cvtX_kernel<<<(MM * HH / 4) / 256, 256>>>((const float4*)X, pXh);
    transW_kernel<<<wgrid, dim3(32, 8)>>>(W_C, pWCh);
    transW_kernel<<<wgrid, dim3(32, 8)>>>(W_A, pWAh);
    transW_kernel<<<wgrid, dim3(32, 8)>>>(w2, pW2h);
    // 2) C = relu(X@W_C + b_C) -> fp16
    gemm_mma<0><<<tgrid, 256, SMEM_GEMM>>>(pXh, pWCh, b_C,
                                           nullptr, pCh, nullptr, nullptr, nullptr);
    // 3) A = relu(X@W_A + b_A) -> fp32 output + fp16
    gemm_mma<1><<<tgrid, 256, SMEM_GEMM>>>(pXh, pWAh, b_A,
                                           A_out, pAh, nullptr, nullptr, nullptr);
    // 4) q = C^T @ item_weights
    colreduce_h<<<dim3(FF / 256, BB, 8), 256>>>(pCh, iw, pq);
    // 5) t1 = q @ w1
    smallgemm_kernel<<<dim3(FF / 256, BB), 256>>>(pq, w1, pt1);
    // 6) alpha_pre = tanh(C@w2 + t1 + bias) . v
    gemm_mma<2><<<tgrid, 256, SMEM_GEMM>>>(pCh, pW2h, attn_bias,
                                           nullptr, nullptr, pt1, v, ppre);
    // 7) softmax
    softmax_kernel<<<BB, 256>>>(ppre, mask, palpha);
    // 8) h = C^T @ alpha
    colreduce_h<<<dim3(FF / 256, BB, 8), 256>>>(pCh, palpha, h_out);
    // 9) t1 = h @ w1
    smallgemm_kernel<<<dim3(FF / 256, BB), 256>>>(h_out, w1, pt1);
    // 10) L_pre = tanh(A@w2 + t1 + bias) . v
    gemm_mma<2><<<tgrid, 256, SMEM_GEMM>>>(pAh, pW2h, attn_bias,
                                           nullptr, nullptr, pt1, v, pLpre);
    // 11) sparsemax
    sparsemax_kernel<<<BB, 1024>>>(pLpre, mask, w_1, w_2s, w_3, layer_i, L_out);
}

// round 6
// speedup vs baseline: 5.5668x; 1.1205x over previous
#include <cuda_runtime.h>
#include <cuda_fp16.h>
#include <math.h>
#include <stdint.h>

#define BB 16
#define SS 2048
#define HH 1024
#define FF 1024
#define MM (BB*SS)   // 32768

// ---------------- device scratch (no runtime allocation allowed) ----------
__device__ __half g_Xh[(size_t)MM*HH];
__device__ __half g_Ch[(size_t)MM*FF];
__device__ __half g_Am[(size_t)MM*FF];
__device__ __half g_WCh[(size_t)FF*HH];
__device__ __half g_WAh[(size_t)FF*HH];
__device__ __half g_W2h[(size_t)FF*FF];
__device__ float g_q[BB*FF];
__device__ float g_t1[BB*FF];
__device__ float g_pre[BB*SS];
__device__ float g_alpha[BB*SS];
__device__ float g_Lpre[BB*SS];

// ---------------------------------------------------------------------------
__device__ __forceinline__ void cpa16(uint32_t s, const void* g) {
    asm volatile("cp.async.cg.shared.global [%0], [%1], 16;" :: "r"(s), "l"(g));
}
__device__ __forceinline__ void cp_commit() {
    asm volatile("cp.async.commit_group;");
}
__device__ __forceinline__ void ldsm4(uint32_t* r, uint32_t a) {
    asm volatile("ldmatrix.sync.aligned.m8n8.x4.shared.b16 {%0,%1,%2,%3}, [%4];"
        : "=r"(r[0]), "=r"(r[1]), "=r"(r[2]), "=r"(r[3]) : "r"(a));
}
__device__ __forceinline__ void mma16816(float* c, const uint32_t* a, const uint32_t* b) {
    asm volatile("mma.sync.aligned.m16n8k16.row.col.f32.f16.f16.f32 "
        "{%0,%1,%2,%3}, {%4,%5,%6,%7}, {%8,%9}, {%0,%1,%2,%3};"
        : "+f"(c[0]), "+f"(c[1]), "+f"(c[2]), "+f"(c[3])
        : "r"(a[0]), "r"(a[1]), "r"(a[2]), "r"(a[3]), "r"(b[0]), "r"(b[1]));
}

// ---------------------------------------------------------------------------
__global__ void zero_kernel(float* q, float* h_out, float* pre, float* lpre) {
    int i = blockIdx.x * 256 + threadIdx.x;
    if (i < BB * FF) { q[i] = 0.f; h_out[i] = 0.f; }
    if (i < BB * SS) { pre[i] = 0.f; lpre[i] = 0.f; }
}

// convert X fp32 -> fp16, 1 float4 per thread
__global__ void cvtX_kernel(const float4* __restrict__ X, __half* __restrict__ Xh) {
    size_t i = (size_t)blockIdx.x * 256 + threadIdx.x;
    float4 v = X[i];
    __half2* p = (__half2*)Xh;
    p[i*2]   = __floats2half2_rn(v.x, v.y);
    p[i*2+1] = __floats2half2_rn(v.z, v.w);
}

// transpose + convert weight: T[n][k] = fp16(W[k][n])
__global__ void transW_kernel(const float* __restrict__ W, __half* __restrict__ T) {
    __shared__ float t[32][33];
    int n0 = blockIdx.x * 32, k0 = blockIdx.y * 32;
    int x = threadIdx.x, y = threadIdx.y;   // 32x8
    #pragma unroll
    for (int d = 0; d < 32; d += 8)
        t[y + d][x] = W[(size_t)(k0 + y + d) * FF + n0 + x];
    __syncthreads();
    #pragma unroll
    for (int d = 0; d < 32; d += 8) {
        int n = n0 + y + d, k = k0 + x;
        T[(size_t)n * HH + k] = __float2half(t[x][y + d]);
    }
}

// ---------------------------------------------------------------------------
// HMMA fp16 GEMM:  D[M,N] = A[M,K] @ B^T[N,K]
// CTA tile 256x128x64, 8 warps (4M x 2N), warp tile 64x64, 3-stage cp.async.
// smem rows: stride 144B (128B data + 16B pad) -> conflict-free ldmatrix.
// MODE 0: relu(acc+bias) -> fp16 out; fused q[b,f] += relu * iw[row]
// MODE 1: relu(acc+bias) -> fp32 out + fp16 out
// MODE 2: p = sum_n tanh(acc + t1[b,n] + bias[n]) * v[n]; atomicAdd(rowdot[m], p)
#define KC 64
#define ROWB 144
#define OFF_A 0
#define OFF_B 36864
#define STAGE_B 55296
#define NSTAGE 3
#define QS_OFF (NSTAGE*STAGE_B)
#define SMEM_GEMM (QS_OFF + 512)   // 166400
#define NCHUNK (HH/KC)             // 16

template <int MODE>
__global__ void __launch_bounds__(256, 1)
gemm_mma(const __half* __restrict__ A_g, const __half* __restrict__ B_g,
         const float* __restrict__ bias,
         float* __restrict__ out_f32, __half* __restrict__ out_h,
         const float* __restrict__ t1, const float* __restrict__ vvec,
         float* __restrict__ rowdot,
         const float* __restrict__ iw, float* __restrict__ q_out)
{
    extern __shared__ char smem[];
    uint32_t sb = (uint32_t)__cvta_generic_to_shared(smem);
    int tid = threadIdx.x, lane = tid & 31, wid = tid >> 5;
    int bn = blockIdx.x, bm = blockIdx.y;

    const __half* Asrc = A_g + (size_t)bm * 256 * HH;
    const __half* Bsrc = B_g + (size_t)bn * 128 * HH;

    int ld_row = tid >> 3;          // 0..31
    int ld_ch  = tid & 7;           // 0..7 (16B chunks)

    // prologue: stages 0, 1
    #pragma unroll
    for (int c = 0; c < NSTAGE - 1; c++) {
        uint32_t buf = sb + c * STAGE_B;
        #pragma unroll
        for (int i = 0; i < 8; i++) {
            int row = ld_row + i * 32;
            cpa16(buf + OFF_A + row * ROWB + ld_ch * 16,
                  Asrc + (size_t)row * HH + c * KC + ld_ch * 8);
        }
        #pragma unroll
        for (int i = 0; i < 4; i++) {
            int row = ld_row + i * 32;
            cpa16(buf + OFF_B + row * ROWB + ld_ch * 16,
                  Bsrc + (size_t)row * HH + c * KC + ld_ch * 8);
        }
        cp_commit();
    }

    float acc[4][8][4];
    #pragma unroll
    for (int mt = 0; mt < 4; mt++)
        #pragma unroll
        for (int nt = 0; nt < 8; nt++)
            #pragma unroll
            for (int e = 0; e < 4; e++) acc[mt][nt][e] = 0.f;

    int warpM = wid & 3, warpN = wid >> 2;
    int m0 = warpM * 64, n0 = warpN * 64;

    uint32_t a_base = (uint32_t)(m0 + (lane & 15)) * ROWB + (uint32_t)(lane >> 4) * 16;
    int b_rowp = ((lane >> 4) << 3) + (lane & 7);
    uint32_t b_base = (uint32_t)(n0 + b_rowp) * ROWB + (uint32_t)((lane >> 3) & 1) * 16;

    for (int c = 0; c < NCHUNK; c++) {
        if (c < NCHUNK - 2) asm volatile("cp.async.wait_group 1;" ::: "memory");
        else                asm volatile("cp.async.wait_group 0;" ::: "memory");
        __syncthreads();

        if (c + NSTAGE - 1 < NCHUNK) {
            uint32_t buf = sb + ((c + NSTAGE - 1) % NSTAGE) * STAGE_B;
            int kc0 = (c + NSTAGE - 1) * KC;
            #pragma unroll
            for (int i = 0; i < 8; i++) {
                int row = ld_row + i * 32;
                cpa16(buf + OFF_A + row * ROWB + ld_ch * 16,
                      Asrc + (size_t)row * HH + kc0 + ld_ch * 8);
            }
            #pragma unroll
            for (int i = 0; i < 4; i++) {
                int row = ld_row + i * 32;
                cpa16(buf + OFF_B + row * ROWB + ld_ch * 16,
                      Bsrc + (size_t)row * HH + kc0 + ld_ch * 8);
            }
        }
        cp_commit();

        uint32_t buf = sb + (c % NSTAGE) * STAGE_B;
        uint32_t As = buf + OFF_A, Bs = buf + OFF_B;

        #pragma unroll
        for (int ks = 0; ks < 4; ks++) {
            uint32_t ah[4][4];
            #pragma unroll
            for (int mt = 0; mt < 4; mt++)
                ldsm4(ah[mt], As + a_base + (uint32_t)mt * (16 * ROWB) + (uint32_t)ks * 32);
            uint32_t bh[8][2];
            #pragma unroll
            for (int p = 0; p < 4; p++) {
                uint32_t r[4];
                ldsm4(r, Bs + b_base + (uint32_t)p * (16 * ROWB) + (uint32_t)ks * 32);
                bh[2*p][0] = r[0]; bh[2*p][1] = r[1];
                bh[2*p+1][0] = r[2]; bh[2*p+1][1] = r[3];
            }
            #pragma unroll
            for (int mt = 0; mt < 4; mt++)
                #pragma unroll
                for (int nt = 0; nt < 8; nt++)
                    mma16816(acc[mt][nt], ah[mt], bh[nt]);
        }
    }

    // ---------------- epilogue ----------------
    int g4 = lane >> 2;           // row-in-8 group
    int cpair = (lane & 3) * 2;   // col pair base

    if (MODE == 2) {
        int batch = bm >> 3;      // 256 rows per bm; 2048 per batch
        #pragma unroll
        for (int mt = 0; mt < 4; mt++) {
            #pragma unroll
            for (int h = 0; h < 2; h++) {
                int grow = bm * 256 + m0 + mt * 16 + g4 + h * 8;
                float p = 0.f;
                #pragma unroll
                for (int nt = 0; nt < 8; nt++) {
                    int n = bn * 128 + n0 + nt * 8 + cpair;
                    #pragma unroll
                    for (int e = 0; e < 2; e++) {
                        float x = acc[mt][nt][h * 2 + e] + t1[batch * FF + n + e] + bias[n + e];
                        p = fmaf(tanhf(x), vvec[n + e], p);
                    }
                }
                p += __shfl_xor_sync(0xffffffffu, p, 1);
                p += __shfl_xor_sync(0xffffffffu, p, 2);
                if ((lane & 3) == 0) atomicAdd(&rowdot[grow], p);
            }
        }
    } else {
        #pragma unroll
        for (int mt = 0; mt < 4; mt++) {
            #pragma unroll
            for (int h = 0; h < 2; h++) {
                int grow = bm * 256 + m0 + mt * 16 + g4 + h * 8;
                #pragma unroll
                for (int nt = 0; nt < 8; nt++) {
                    int n = bn * 128 + n0 + nt * 8 + cpair;
                    float v0 = acc[mt][nt][h * 2 + 0] + bias[n + 0];
                    float v1 = acc[mt][nt][h * 2 + 1] + bias[n + 1];
                    v0 = v0 > 0.f ? v0 : 0.f;
                    v1 = v1 > 0.f ? v1 : 0.f;
                    if (MODE == 1)
                        *(float2*)(out_f32 + (size_t)grow * FF + n) = make_float2(v0, v1);
                    *(__half2*)(out_h + (size_t)grow * FF + n) = __floats2half2_rn(v0, v1);
                }
            }
        }
        if (MODE == 0) {
            // fused q[b,f] += sum_rows relu(acc+bias) * iw[row]
            float* qs_red = (float*)(smem + QS_OFF);
            if (tid < 128) qs_red[tid] = 0.f;
            __syncthreads();
            float iwv[4][2];
            #pragma unroll
            for (int mt = 0; mt < 4; mt++)
                #pragma unroll
                for (int h = 0; h < 2; h++)
                    iwv[mt][h] = iw[bm * 256 + m0 + mt * 16 + g4 + h * 8];
            #pragma unroll
            for (int nt = 0; nt < 8; nt++) {
                #pragma unroll
                for (int e = 0; e < 2; e++) {
                    int n = bn * 128 + n0 + nt * 8 + cpair + e;
                    float p = 0.f;
                    #pragma unroll
                    for (int mt = 0; mt < 4; mt++)
                        #pragma unroll
                        for (int h = 0; h < 2; h++) {
                            float vv = acc[mt][nt][h * 2 + e] + bias[n];
                            vv = vv > 0.f ? vv : 0.f;
                            p = fmaf(vv, iwv[mt][h], p);
                        }
                    p += __shfl_xor_sync(0xffffffffu, p, 4);
                    p += __shfl_xor_sync(0xffffffffu, p, 8);
                    p += __shfl_xor_sync(0xffffffffu, p, 16);
                    if (g4 == 0)
                        atomicAdd(&qs_red[n0 + nt * 8 + cpair + e], p);
                }
            }
            __syncthreads();
            if (tid < 128)
                atomicAdd(&q_out[(bm >> 3) * FF + bn * 128 + tid], qs_red[tid]);
        }
    }
}

// ---------------------------------------------------------------------------
// out[b,f] += sum_s X[b,s,f] * w[b,s]
__global__ void colreduce_h(const __half* __restrict__ Xh,
                            const float* __restrict__ w,
                            float* __restrict__ out)
{
    int f = blockIdx.x * 256 + threadIdx.x;
    int b = blockIdx.y;
    int s0 = blockIdx.z * 256;
    const __half* hp = Xh + ((size_t)b * SS + s0) * FF + f;
    const float* wp = w + b * SS + s0;
    float acc = 0.f;
    #pragma unroll 4
    for (int s = 0; s < 256; s++)
        acc = fmaf(__half2float(hp[(size_t)s * FF]), wp[s], acc);
    atomicAdd(&out[b * FF + f], acc);
}

// t1[b,n] = sum_k q[b,k] * w1[k,n]
__global__ void smallgemm_kernel(const float* __restrict__ q,
                                 const float* __restrict__ w1,
                                 float* __restrict__ t1)
{
    __shared__ float qs[256];
    int n = blockIdx.x * 256 + threadIdx.x;
    int b = blockIdx.y;
    float acc = 0.f;
    for (int k0 = 0; k0 < FF; k0 += 256) {
        __syncthreads();
        qs[threadIdx.x] = q[b * FF + k0 + threadIdx.x];
        __syncthreads();
        #pragma unroll 8
        for (int k = 0; k < 256; k++)
            acc = fmaf(qs[k], w1[(size_t)(k0 + k) * FF + n], acc);
    }
    t1[b * FF + n] = acc;
}

// ---------------------------------------------------------------------------
__device__ __forceinline__ float blockReduce(float v, bool do_max) {
    __shared__ float sm[32];
    __syncthreads();
    int lane = threadIdx.x & 31, wid = threadIdx.x >> 5;
    #pragma unroll
    for (int o = 16; o; o >>= 1) {
        float t = __shfl_down_sync(0xffffffffu, v, o);
        v = do_max ? fmaxf(v, t) : v + t;
    }
    if (lane == 0) sm[wid] = v;
    __syncthreads();
    int nw = blockDim.x >> 5;
    v = (threadIdx.x < nw) ? sm[threadIdx.x] : (do_max ? -1e30f : 0.f);
    if (wid == 0) {
        #pragma unroll
        for (int o = 16; o; o >>= 1) {
            float t = __shfl_down_sync(0xffffffffu, v, o);
            v = do_max ? fmaxf(v, t) : v + t;
        }
        if (lane == 0) sm[0] = v;
    }
    __syncthreads();
    return sm[0];
}

__global__ void softmax_kernel(const float* __restrict__ pre,
                               const float* __restrict__ mask,
                               float* __restrict__ alpha)
{
    int b = blockIdx.x, tid = threadIdx.x;
    float z[8];
    float mx = -1e30f;
    #pragma unroll
    for (int i = 0; i < 8; i++) {
        int s = tid + i * 256;
        z[i] = pre[b * SS + s] + (1.f - mask[b * SS + s]) * -10000.f;
        mx = fmaxf(mx, z[i]);
    }
    mx = blockReduce(mx, true);
    float sum = 0.f;
    #pragma unroll
    for (int i = 0; i < 8; i++) { z[i] = expf(z[i] - mx); sum += z[i]; }
    sum = blockReduce(sum, false);
    float inv = 1.f / sum;
    #pragma unroll
    for (int i = 0; i < 8; i++)
        alpha[b * SS + tid + i * 256] = z[i] * inv;
}

__global__ void sparsemax_kernel(const float* __restrict__ Lpre,
                                 const float* __restrict__ mask,
                                 const float* __restrict__ w_1,
                                 const float* __restrict__ w_2,
                                 const float* __restrict__ w_3,
                                 const int* __restrict__ layer_i,
                                 float* __restrict__ Lout)
{
    __shared__ float zs[SS];
    __shared__ float cum[SS];
    __shared__ int scnt;
    int b = blockIdx.x, tid = threadIdx.x;

    int li = layer_i[0];
    float a1 = w_1[0], a2 = w_2[0], a3 = w_3[0];
    float x;
    if (li == 0)      x = a3 * a3 - a2 * a2 - a1 * a1;
    else if (li == 1) x = a3 * a3 - a2 * a2;
    else              x = a3 * a3;
    float sig = 1.f / (1.f + expf(-x));

    for (int i = tid; i < SS; i += 1024)
        zs[i] = Lpre[b * SS + i] * sig + (1.f - mask[b * SS + i]) * -10000.f;
    if (tid == 0) scnt = 0;
    __syncthreads();

    for (int k = 2; k <= SS; k <<= 1) {
        for (int j = k >> 1; j > 0; j >>= 1) {
            for (int t = tid; t < SS; t += 1024) {
                int ixj = t ^ j;
                if (ixj > t) {
                    float a = zs[t], c = zs[ixj];
                    bool up = ((t & k) == 0);
                    if ((a > c) == up) { zs[t] = c; zs[ixj] = a; }
                }
            }
            __syncthreads();
        }
    }

    cum[tid]        = zs[SS - 1 - tid];
    cum[tid + 1024] = zs[SS - 1 - (tid + 1024)];
    __syncthreads();
    for (int off = 1; off < SS; off <<= 1) {
        float v0 = (tid >= off) ? cum[tid - off] : 0.f;
        float v1 = cum[tid + 1024 - off];
        __syncthreads();
        cum[tid] += v0;
        cum[tid + 1024] += v1;
        __syncthreads();
    }

    int c = 0;
    #pragma unroll
    for (int r = 0; r < 2; r++) {
        int i = tid + r * 1024;
        if (1.f + (float)(i + 1) * zs[SS - 1 - i] > cum[i]) c++;
    }
    atomicAdd(&scnt, c);
    __syncthreads();
    int ks = scnt;
    float tau = (cum[ks - 1] - 1.f) / (float)ks;

    for (int i = tid; i < SS; i += 1024) {
        float zv = Lpre[b * SS + i] * sig + (1.f - mask[b * SS + i]) * -10000.f;
        Lout[b * SS + i] = fmaxf(zv - tau, 0.f);
    }
}

// ---------------------------------------------------------------------------
extern "C" void kernel_launch(void* const* d_in, const int* in_sizes, int n_in,
                              void* d_out, int out_size)
{
    const float* mask      = (const float*)d_in[0];
    const float* X         = (const float*)d_in[1];
    const float* iw        = (const float*)d_in[2];
    const float* W_C       = (const float*)d_in[3];
    const float* b_C       = (const float*)d_in[4];
    const float* W_A       = (const float*)d_in[5];
    const float* b_A       = (const float*)d_in[6];
    const float* w1        = (const float*)d_in[7];
    const float* w2        = (const float*)d_in[8];
    const float* attn_bias = (const float*)d_in[9];
    const float* v         = (const float*)d_in[10];
    const float* w_1       = (const float*)d_in[11];
    const float* w_2s      = (const float*)d_in[12];
    const float* w_3       = (const float*)d_in[13];
    const int*   layer_i   = (const int*)d_in[14];

    float* out   = (float*)d_out;
    float* h_out = out;
    float* L_out = out + BB * FF;
    float* A_out = out + BB * FF + BB * SS;

    __half *pXh, *pCh, *pAh, *pWCh, *pWAh, *pW2h;
    float *pq, *pt1, *ppre, *palpha, *pLpre;
    cudaGetSymbolAddress((void**)&pXh, g_Xh);
    cudaGetSymbolAddress((void**)&pCh, g_Ch);
    cudaGetSymbolAddress((void**)&pAh, g_Am);
    cudaGetSymbolAddress((void**)&pWCh, g_WCh);
    cudaGetSymbolAddress((void**)&pWAh, g_WAh);
    cudaGetSymbolAddress((void**)&pW2h, g_W2h);
    cudaGetSymbolAddress((void**)&pq, g_q);
    cudaGetSymbolAddress((void**)&pt1, g_t1);
    cudaGetSymbolAddress((void**)&ppre, g_pre);
    cudaGetSymbolAddress((void**)&palpha, g_alpha);
    cudaGetSymbolAddress((void**)&pLpre, g_Lpre);

    cudaFuncSetAttribute(gemm_mma<0>, cudaFuncAttributeMaxDynamicSharedMemorySize, SMEM_GEMM);
    cudaFuncSetAttribute(gemm_mma<1>, cudaFuncAttributeMaxDynamicSharedMemorySize, SMEM_GEMM);
    cudaFuncSetAttribute(gemm_mma<2>, cudaFuncAttributeMaxDynamicSharedMemorySize, SMEM_GEMM);

    dim3 tgrid(FF / 128, MM / 256);   // (8, 128) — n fastest for A-tile L2 reuse
    dim3 wgrid(FF / 32, HH / 32);

    // 0) zero accumulators
    zero_kernel<<<128, 256>>>(pq, h_out, ppre, pLpre);
    // 1) prep: convert X; transpose+convert weights
    cvtX_kernel<<<(MM * HH / 4) / 256, 256>>>((const float4*)X, pXh);
    transW_kernel<<<wgrid, dim3(32, 8)>>>(W_C, pWCh);
    transW_kernel<<<wgrid, dim3(32, 8)>>>(W_A, pWAh);
    transW_kernel<<<wgrid, dim3(32, 8)>>>(w2, pW2h);
    // 2) C = relu(X@W_C + b_C) -> fp16; fused q = C^T @ item_weights
    gemm_mma<0><<<tgrid, 256, SMEM_GEMM>>>(pXh, pWCh, b_C,
                                           nullptr, pCh, nullptr, nullptr, nullptr,
                                           iw, pq);
    // 3) A = relu(X@W_A + b_A) -> fp32 output + fp16
    gemm_mma<1><<<tgrid, 256, SMEM_GEMM>>>(pXh, pWAh, b_A,
                                           A_out, pAh, nullptr, nullptr, nullptr,
                                           nullptr, nullptr);
    // 4) t1 = q @ w1
    smallgemm_kernel<<<dim3(FF / 256, BB), 256>>>(pq, w1, pt1);
    // 5) alpha_pre = tanh(C@w2 + t1 + bias) . v
    gemm_mma<2><<<tgrid, 256, SMEM_GEMM>>>(pCh, pW2h, attn_bias,
                                           nullptr, nullptr, pt1, v, ppre,
                                           nullptr, nullptr);
    // 6) softmax
    softmax_kernel<<<BB, 256>>>(ppre, mask, palpha);
    // 7) h = C^T @ alpha
    colreduce_h<<<dim3(FF / 256, BB, 8), 256>>>(pCh, palpha, h_out);
    // 8) t1 = h @ w1
    smallgemm_kernel<<<dim3(FF / 256, BB), 256>>>(h_out, w1, pt1);
    // 9) L_pre = tanh(A@w2 + t1 + bias) . v
    gemm_mma<2><<<tgrid, 256, SMEM_GEMM>>>(pAh, pW2h, attn_bias,
                                           nullptr, nullptr, pt1, v, pLpre,
                                           nullptr, nullptr);
    // 10) sparsemax
    sparsemax_kernel<<<BB, 1024>>>(pLpre, mask, w_1, w_2s, w_3, layer_i, L_out);
}

// round 7
// speedup vs baseline: 6.1121x; 1.0980x over previous
#include <cuda_runtime.h>
#include <cuda_fp16.h>
#include <math.h>
#include <stdint.h>

#define BB 16
#define SS 2048
#define HH 1024
#define FF 1024
#define MM (BB*SS)   // 32768

// ---------------- device scratch (no runtime allocation allowed) ----------
__device__ __half g_Xh[(size_t)MM*HH];
__device__ __half g_Ch[(size_t)MM*FF];
__device__ __half g_Am[(size_t)MM*FF];
__device__ __half g_WCh[(size_t)FF*HH];
__device__ __half g_WAh[(size_t)FF*HH];
__device__ __half g_W2h[(size_t)FF*FF];
__device__ float g_q[BB*FF];
__device__ float g_t1[BB*FF];
__device__ float g_pre[BB*SS];
__device__ float g_alpha[BB*SS];
__device__ float g_Lpre[BB*SS];

// ---------------------------------------------------------------------------
__device__ __forceinline__ void cpa16(uint32_t s, const void* g) {
    asm volatile("cp.async.cg.shared.global [%0], [%1], 16;" :: "r"(s), "l"(g));
}
__device__ __forceinline__ void cp_commit() {
    asm volatile("cp.async.commit_group;");
}
__device__ __forceinline__ void ldsm4(uint32_t* r, uint32_t a) {
    asm volatile("ldmatrix.sync.aligned.m8n8.x4.shared.b16 {%0,%1,%2,%3}, [%4];"
        : "=r"(r[0]), "=r"(r[1]), "=r"(r[2]), "=r"(r[3]) : "r"(a));
}
__device__ __forceinline__ void mma16816(float* c, const uint32_t* a, const uint32_t* b) {
    asm volatile("mma.sync.aligned.m16n8k16.row.col.f32.f16.f16.f32 "
        "{%0,%1,%2,%3}, {%4,%5,%6,%7}, {%8,%9}, {%0,%1,%2,%3};"
        : "+f"(c[0]), "+f"(c[1]), "+f"(c[2]), "+f"(c[3])
        : "r"(a[0]), "r"(a[1]), "r"(a[2]), "r"(a[3]), "r"(b[0]), "r"(b[1]));
}

// ---------------------------------------------------------------------------
__global__ void zero_kernel(float* q, float* h_out, float* pre, float* lpre) {
    int i = blockIdx.x * 256 + threadIdx.x;
    if (i < BB * FF) { q[i] = 0.f; h_out[i] = 0.f; }
    if (i < BB * SS) { pre[i] = 0.f; lpre[i] = 0.f; }
}

// convert X fp32 -> fp16, 1 float4 per thread
__global__ void cvtX_kernel(const float4* __restrict__ X, __half* __restrict__ Xh) {
    size_t i = (size_t)blockIdx.x * 256 + threadIdx.x;
    float4 v = X[i];
    __half2* p = (__half2*)Xh;
    p[i*2]   = __floats2half2_rn(v.x, v.y);
    p[i*2+1] = __floats2half2_rn(v.z, v.w);
}

// transpose + convert weight: T[n][k] = fp16(W[k][n])
__global__ void transW_kernel(const float* __restrict__ W, __half* __restrict__ T) {
    __shared__ float t[32][33];
    int n0 = blockIdx.x * 32, k0 = blockIdx.y * 32;
    int x = threadIdx.x, y = threadIdx.y;   // 32x8
    #pragma unroll
    for (int d = 0; d < 32; d += 8)
        t[y + d][x] = W[(size_t)(k0 + y + d) * FF + n0 + x];
    __syncthreads();
    #pragma unroll
    for (int d = 0; d < 32; d += 8) {
        int n = n0 + y + d, k = k0 + x;
        T[(size_t)n * HH + k] = __float2half(t[x][y + d]);
    }
}

// ---------------------------------------------------------------------------
// HMMA fp16 GEMM:  D[M,N] = A[M,K] @ B^T[N,K]
// CTA tile 256x128x64, 8 warps (4M x 2N), warp tile 64x64, 3-stage cp.async.
#define KC 64
#define ROWB 144
#define OFF_A 0
#define OFF_B 36864
#define STAGE_B 55296
#define NSTAGE 3
#define QS_OFF (NSTAGE*STAGE_B)
#define SMEM_GEMM (QS_OFF + 512)   // 166400
#define NCHUNK (HH/KC)             // 16

template <int MODE>
__global__ void __launch_bounds__(256, 1)
gemm_mma(const __half* __restrict__ A_g, const __half* __restrict__ B_g,
         const float* __restrict__ bias,
         float* __restrict__ out_f32, __half* __restrict__ out_h,
         const float* __restrict__ t1, const float* __restrict__ vvec,
         float* __restrict__ rowdot,
         const float* __restrict__ iw, float* __restrict__ q_out)
{
    extern __shared__ char smem[];
    uint32_t sb = (uint32_t)__cvta_generic_to_shared(smem);
    int tid = threadIdx.x, lane = tid & 31, wid = tid >> 5;
    int bn = blockIdx.x, bm = blockIdx.y;

    const __half* Asrc = A_g + (size_t)bm * 256 * HH;
    const __half* Bsrc = B_g + (size_t)bn * 128 * HH;

    int ld_row = tid >> 3;          // 0..31
    int ld_ch  = tid & 7;           // 0..7 (16B chunks)

    // prologue: stages 0, 1
    #pragma unroll
    for (int c = 0; c < NSTAGE - 1; c++) {
        uint32_t buf = sb + c * STAGE_B;
        #pragma unroll
        for (int i = 0; i < 8; i++) {
            int row = ld_row + i * 32;
            cpa16(buf + OFF_A + row * ROWB + ld_ch * 16,
                  Asrc + (size_t)row * HH + c * KC + ld_ch * 8);
        }
        #pragma unroll
        for (int i = 0; i < 4; i++) {
            int row = ld_row + i * 32;
            cpa16(buf + OFF_B + row * ROWB + ld_ch * 16,
                  Bsrc + (size_t)row * HH + c * KC + ld_ch * 8);
        }
        cp_commit();
    }

    float acc[4][8][4];
    #pragma unroll
    for (int mt = 0; mt < 4; mt++)
        #pragma unroll
        for (int nt = 0; nt < 8; nt++)
            #pragma unroll
            for (int e = 0; e < 4; e++) acc[mt][nt][e] = 0.f;

    int warpM = wid & 3, warpN = wid >> 2;
    int m0 = warpM * 64, n0 = warpN * 64;

    uint32_t a_base = (uint32_t)(m0 + (lane & 15)) * ROWB + (uint32_t)(lane >> 4) * 16;
    int b_rowp = ((lane >> 4) << 3) + (lane & 7);
    uint32_t b_base = (uint32_t)(n0 + b_rowp) * ROWB + (uint32_t)((lane >> 3) & 1) * 16;

    for (int c = 0; c < NCHUNK; c++) {
        if (c < NCHUNK - 2) asm volatile("cp.async.wait_group 1;" ::: "memory");
        else                asm volatile("cp.async.wait_group 0;" ::: "memory");
        __syncthreads();

        if (c + NSTAGE - 1 < NCHUNK) {
            uint32_t buf = sb + ((c + NSTAGE - 1) % NSTAGE) * STAGE_B;
            int kc0 = (c + NSTAGE - 1) * KC;
            #pragma unroll
            for (int i = 0; i < 8; i++) {
                int row = ld_row + i * 32;
                cpa16(buf + OFF_A + row * ROWB + ld_ch * 16,
                      Asrc + (size_t)row * HH + kc0 + ld_ch * 8);
            }
            #pragma unroll
            for (int i = 0; i < 4; i++) {
                int row = ld_row + i * 32;
                cpa16(buf + OFF_B + row * ROWB + ld_ch * 16,
                      Bsrc + (size_t)row * HH + kc0 + ld_ch * 8);
            }
        }
        cp_commit();

        uint32_t buf = sb + (c % NSTAGE) * STAGE_B;
        uint32_t As = buf + OFF_A, Bs = buf + OFF_B;

        #pragma unroll
        for (int ks = 0; ks < 4; ks++) {
            uint32_t ah[4][4];
            #pragma unroll
            for (int mt = 0; mt < 4; mt++)
                ldsm4(ah[mt], As + a_base + (uint32_t)mt * (16 * ROWB) + (uint32_t)ks * 32);
            uint32_t bh[8][2];
            #pragma unroll
            for (int p = 0; p < 4; p++) {
                uint32_t r[4];
                ldsm4(r, Bs + b_base + (uint32_t)p * (16 * ROWB) + (uint32_t)ks * 32);
                bh[2*p][0] = r[0]; bh[2*p][1] = r[1];
                bh[2*p+1][0] = r[2]; bh[2*p+1][1] = r[3];
            }
            #pragma unroll
            for (int mt = 0; mt < 4; mt++)
                #pragma unroll
                for (int nt = 0; nt < 8; nt++)
                    mma16816(acc[mt][nt], ah[mt], bh[nt]);
        }
    }

    // ---------------- epilogue ----------------
    int g4 = lane >> 2;           // row-in-8 group
    int cpair = (lane & 3) * 2;   // col pair base

    if (MODE == 2) {
        int batch = bm >> 3;      // 256 rows per bm; 2048 per batch
        #pragma unroll
        for (int mt = 0; mt < 4; mt++) {
            #pragma unroll
            for (int h = 0; h < 2; h++) {
                int grow = bm * 256 + m0 + mt * 16 + g4 + h * 8;
                float p = 0.f;
                #pragma unroll
                for (int nt = 0; nt < 8; nt++) {
                    int n = bn * 128 + n0 + nt * 8 + cpair;
                    #pragma unroll
                    for (int e = 0; e < 2; e++) {
                        float x = acc[mt][nt][h * 2 + e] + t1[batch * FF + n + e] + bias[n + e];
                        p = fmaf(tanhf(x), vvec[n + e], p);
                    }
                }
                p += __shfl_xor_sync(0xffffffffu, p, 1);
                p += __shfl_xor_sync(0xffffffffu, p, 2);
                if ((lane & 3) == 0) atomicAdd(&rowdot[grow], p);
            }
        }
    } else {
        #pragma unroll
        for (int mt = 0; mt < 4; mt++) {
            #pragma unroll
            for (int h = 0; h < 2; h++) {
                int grow = bm * 256 + m0 + mt * 16 + g4 + h * 8;
                #pragma unroll
                for (int nt = 0; nt < 8; nt++) {
                    int n = bn * 128 + n0 + nt * 8 + cpair;
                    float v0 = acc[mt][nt][h * 2 + 0] + bias[n + 0];
                    float v1 = acc[mt][nt][h * 2 + 1] + bias[n + 1];
                    v0 = v0 > 0.f ? v0 : 0.f;
                    v1 = v1 > 0.f ? v1 : 0.f;
                    if (MODE == 1)
                        *(float2*)(out_f32 + (size_t)grow * FF + n) = make_float2(v0, v1);
                    *(__half2*)(out_h + (size_t)grow * FF + n) = __floats2half2_rn(v0, v1);
                }
            }
        }
        if (MODE == 0) {
            // fused q[b,f] += sum_rows relu(acc+bias) * iw[row]
            float* qs_red = (float*)(smem + QS_OFF);
            if (tid < 128) qs_red[tid] = 0.f;
            __syncthreads();
            float iwv[4][2];
            #pragma unroll
            for (int mt = 0; mt < 4; mt++)
                #pragma unroll
                for (int h = 0; h < 2; h++)
                    iwv[mt][h] = iw[bm * 256 + m0 + mt * 16 + g4 + h * 8];
            #pragma unroll
            for (int nt = 0; nt < 8; nt++) {
                #pragma unroll
                for (int e = 0; e < 2; e++) {
                    int n = bn * 128 + n0 + nt * 8 + cpair + e;
                    float p = 0.f;
                    #pragma unroll
                    for (int mt = 0; mt < 4; mt++)
                        #pragma unroll
                        for (int h = 0; h < 2; h++) {
                            float vv = acc[mt][nt][h * 2 + e] + bias[n];
                            vv = vv > 0.f ? vv : 0.f;
                            p = fmaf(vv, iwv[mt][h], p);
                        }
                    p += __shfl_xor_sync(0xffffffffu, p, 4);
                    p += __shfl_xor_sync(0xffffffffu, p, 8);
                    p += __shfl_xor_sync(0xffffffffu, p, 16);
                    if (g4 == 0)
                        atomicAdd(&qs_red[n0 + nt * 8 + cpair + e], p);
                }
            }
            __syncthreads();
            if (tid < 128)
                atomicAdd(&q_out[(bm >> 3) * FF + bn * 128 + tid], qs_red[tid]);
        }
    }
}

// ---------------------------------------------------------------------------
// out[b,f] += sum_s X[b,s,f] * w[b,s]  — 2 columns per thread via __half2
__global__ void colreduce_h(const __half* __restrict__ Xh,
                            const float* __restrict__ w,
                            float* __restrict__ out)
{
    int f2 = blockIdx.x * 256 + threadIdx.x;   // pair index, 0..511
    int b = blockIdx.y;
    int s0 = blockIdx.z * 256;
    const __half2* hp = (const __half2*)(Xh + ((size_t)b * SS + s0) * FF) + f2;
    const float* wp = w + b * SS + s0;
    float a0 = 0.f, a1 = 0.f;
    #pragma unroll 4
    for (int s = 0; s < 256; s++) {
        float2 cv = __half22float2(hp[(size_t)s * (FF/2)]);
        float ww = wp[s];
        a0 = fmaf(cv.x, ww, a0);
        a1 = fmaf(cv.y, ww, a1);
    }
    atomicAdd(&out[b * FF + f2 * 2], a0);
    atomicAdd(&out[b * FF + f2 * 2 + 1], a1);
}

// t1[b,n] += sum_k q[b,k0+k] * w1[k0+k,n]   (k-split via blockIdx.z, atomic)
__global__ void smallgemm_kernel(const float* __restrict__ q,
                                 const float* __restrict__ w1,
                                 float* __restrict__ t1)
{
    __shared__ float qs[256];
    int n = blockIdx.x * 256 + threadIdx.x;
    int b = blockIdx.y;
    int k0 = blockIdx.z * 256;
    qs[threadIdx.x] = q[b * FF + k0 + threadIdx.x];
    __syncthreads();
    float acc = 0.f;
    #pragma unroll 8
    for (int k = 0; k < 256; k++)
        acc = fmaf(qs[k], w1[(size_t)(k0 + k) * FF + n], acc);
    atomicAdd(&t1[b * FF + n], acc);
}

__global__ void zero_t1(float* t1) {
    t1[blockIdx.x * 256 + threadIdx.x] = 0.f;
}

// ---------------------------------------------------------------------------
__device__ __forceinline__ float blockReduce(float v, bool do_max) {
    __shared__ float sm[32];
    __syncthreads();
    int lane = threadIdx.x & 31, wid = threadIdx.x >> 5;
    #pragma unroll
    for (int o = 16; o; o >>= 1) {
        float t = __shfl_down_sync(0xffffffffu, v, o);
        v = do_max ? fmaxf(v, t) : v + t;
    }
    if (lane == 0) sm[wid] = v;
    __syncthreads();
    int nw = blockDim.x >> 5;
    v = (threadIdx.x < nw) ? sm[threadIdx.x] : (do_max ? -1e30f : 0.f);
    if (wid == 0) {
        #pragma unroll
        for (int o = 16; o; o >>= 1) {
            float t = __shfl_down_sync(0xffffffffu, v, o);
            v = do_max ? fmaxf(v, t) : v + t;
        }
        if (lane == 0) sm[0] = v;
    }
    __syncthreads();
    return sm[0];
}

__global__ void softmax_kernel(const float* __restrict__ pre,
                               const float* __restrict__ mask,
                               float* __restrict__ alpha)
{
    int b = blockIdx.x, tid = threadIdx.x;
    float z[8];
    float mx = -1e30f;
    #pragma unroll
    for (int i = 0; i < 8; i++) {
        int s = tid + i * 256;
        z[i] = pre[b * SS + s] + (1.f - mask[b * SS + s]) * -10000.f;
        mx = fmaxf(mx, z[i]);
    }
    mx = blockReduce(mx, true);
    float sum = 0.f;
    #pragma unroll
    for (int i = 0; i < 8; i++) { z[i] = expf(z[i] - mx); sum += z[i]; }
    sum = blockReduce(sum, false);
    float inv = 1.f / sum;
    #pragma unroll
    for (int i = 0; i < 8; i++)
        alpha[b * SS + tid + i * 256] = z[i] * inv;
}

__global__ void sparsemax_kernel(const float* __restrict__ Lpre,
                                 const float* __restrict__ mask,
                                 const float* __restrict__ w_1,
                                 const float* __restrict__ w_2,
                                 const float* __restrict__ w_3,
                                 const int* __restrict__ layer_i,
                                 float* __restrict__ Lout)
{
    __shared__ float zs[SS];
    __shared__ float cum[SS];
    __shared__ int scnt;
    int b = blockIdx.x, tid = threadIdx.x;

    int li = layer_i[0];
    float a1 = w_1[0], a2 = w_2[0], a3 = w_3[0];
    float x;
    if (li == 0)      x = a3 * a3 - a2 * a2 - a1 * a1;
    else if (li == 1) x = a3 * a3 - a2 * a2;
    else              x = a3 * a3;
    float sig = 1.f / (1.f + expf(-x));

    for (int i = tid; i < SS; i += 1024)
        zs[i] = Lpre[b * SS + i] * sig + (1.f - mask[b * SS + i]) * -10000.f;
    if (tid == 0) scnt = 0;
    __syncthreads();

    for (int k = 2; k <= SS; k <<= 1) {
        for (int j = k >> 1; j > 0; j >>= 1) {
            for (int t = tid; t < SS; t += 1024) {
                int ixj = t ^ j;
                if (ixj > t) {
                    float a = zs[t], c = zs[ixj];
                    bool up = ((t & k) == 0);
                    if ((a > c) == up) { zs[t] = c; zs[ixj] = a; }
                }
            }
            __syncthreads();
        }
    }

    cum[tid]        = zs[SS - 1 - tid];
    cum[tid + 1024] = zs[SS - 1 - (tid + 1024)];
    __syncthreads();
    for (int off = 1; off < SS; off <<= 1) {
        float v0 = (tid >= off) ? cum[tid - off] : 0.f;
        float v1 = cum[tid + 1024 - off];
        __syncthreads();
        cum[tid] += v0;
        cum[tid + 1024] += v1;
        __syncthreads();
    }

    int c = 0;
    #pragma unroll
    for (int r = 0; r < 2; r++) {
        int i = tid + r * 1024;
        if (1.f + (float)(i + 1) * zs[SS - 1 - i] > cum[i]) c++;
    }
    atomicAdd(&scnt, c);
    __syncthreads();
    int ks = scnt;
    float tau = (cum[ks - 1] - 1.f) / (float)ks;

    for (int i = tid; i < SS; i += 1024) {
        float zv = Lpre[b * SS + i] * sig + (1.f - mask[b * SS + i]) * -10000.f;
        Lout[b * SS + i] = fmaxf(zv - tau, 0.f);
    }
}

// ---------------------------------------------------------------------------
extern "C" void kernel_launch(void* const* d_in, const int* in_sizes, int n_in,
                              void* d_out, int out_size)
{
    const float* mask      = (const float*)d_in[0];
    const float* X         = (const float*)d_in[1];
    const float* iw        = (const float*)d_in[2];
    const float* W_C       = (const float*)d_in[3];
    const float* b_C       = (const float*)d_in[4];
    const float* W_A       = (const float*)d_in[5];
    const float* b_A       = (const float*)d_in[6];
    const float* w1        = (const float*)d_in[7];
    const float* w2        = (const float*)d_in[8];
    const float* attn_bias = (const float*)d_in[9];
    const float* v         = (const float*)d_in[10];
    const float* w_1       = (const float*)d_in[11];
    const float* w_2s      = (const float*)d_in[12];
    const float* w_3       = (const float*)d_in[13];
    const int*   layer_i   = (const int*)d_in[14];

    float* out   = (float*)d_out;
    float* h_out = out;
    float* L_out = out + BB * FF;
    float* A_out = out + BB * FF + BB * SS;

    __half *pXh, *pCh, *pAh, *pWCh, *pWAh, *pW2h;
    float *pq, *pt1, *ppre, *palpha, *pLpre;
    cudaGetSymbolAddress((void**)&pXh, g_Xh);
    cudaGetSymbolAddress((void**)&pCh, g_Ch);
    cudaGetSymbolAddress((void**)&pAh, g_Am);
    cudaGetSymbolAddress((void**)&pWCh, g_WCh);
    cudaGetSymbolAddress((void**)&pWAh, g_WAh);
    cudaGetSymbolAddress((void**)&pW2h, g_W2h);
    cudaGetSymbolAddress((void**)&pq, g_q);
    cudaGetSymbolAddress((void**)&pt1, g_t1);
    cudaGetSymbolAddress((void**)&ppre, g_pre);
    cudaGetSymbolAddress((void**)&palpha, g_alpha);
    cudaGetSymbolAddress((void**)&pLpre, g_Lpre);

    cudaFuncSetAttribute(gemm_mma<0>, cudaFuncAttributeMaxDynamicSharedMemorySize, SMEM_GEMM);
    cudaFuncSetAttribute(gemm_mma<1>, cudaFuncAttributeMaxDynamicSharedMemorySize, SMEM_GEMM);
    cudaFuncSetAttribute(gemm_mma<2>, cudaFuncAttributeMaxDynamicSharedMemorySize, SMEM_GEMM);

    dim3 tgrid(FF / 128, MM / 256);   // (8, 128) — n fastest for A-tile L2 reuse
    dim3 wgrid(FF / 32, HH / 32);

    // side stream + events for forked capture (A-GEMM concurrent with alpha chain)
    cudaStream_t s2;
    cudaStreamCreateWithFlags(&s2, cudaStreamNonBlocking);
    cudaEvent_t e0, e1, e2;
    cudaEventCreateWithFlags(&e0, cudaEventDisableTiming);
    cudaEventCreateWithFlags(&e1, cudaEventDisableTiming);
    cudaEventCreateWithFlags(&e2, cudaEventDisableTiming);

    // ---- main stream: prep ----
    zero_kernel<<<128, 256>>>(pq, h_out, ppre, pLpre);
    cudaEventRecord(e0, 0);                        // fork point for s2
    cvtX_kernel<<<(MM * HH / 4) / 256, 256>>>((const float4*)X, pXh);
    cudaEventRecord(e1, 0);                        // Xh ready
    transW_kernel<<<wgrid, dim3(32, 8)>>>(W_C, pWCh);
    transW_kernel<<<wgrid, dim3(32, 8)>>>(w2, pW2h);

    // ---- side stream: A = relu(X@W_A + b_A) ----
    cudaStreamWaitEvent(s2, e0, 0);
    transW_kernel<<<wgrid, dim3(32, 8), 0, s2>>>(W_A, pWAh);
    cudaStreamWaitEvent(s2, e1, 0);
    gemm_mma<1><<<tgrid, 256, SMEM_GEMM, s2>>>(pXh, pWAh, b_A,
                                               A_out, pAh, nullptr, nullptr, nullptr,
                                               nullptr, nullptr);
    cudaEventRecord(e2, s2);

    // ---- main stream: C chain ----
    // C = relu(X@W_C + b_C) -> fp16; fused q = C^T @ item_weights
    gemm_mma<0><<<tgrid, 256, SMEM_GEMM>>>(pXh, pWCh, b_C,
                                           nullptr, pCh, nullptr, nullptr, nullptr,
                                           iw, pq);
    // t1 = q @ w1
    zero_t1<<<BB * FF / 256, 256>>>(pt1);
    smallgemm_kernel<<<dim3(FF / 256, BB, 4), 256>>>(pq, w1, pt1);
    // alpha_pre = tanh(C@w2 + t1 + bias) . v
    gemm_mma<2><<<tgrid, 256, SMEM_GEMM>>>(pCh, pW2h, attn_bias,
                                           nullptr, nullptr, pt1, v, ppre,
                                           nullptr, nullptr);
    // softmax
    softmax_kernel<<<BB, 256>>>(ppre, mask, palpha);
    // h = C^T @ alpha
    colreduce_h<<<dim3(FF / 512, BB, 8), 256>>>(pCh, palpha, h_out);
    // t1 = h @ w1
    zero_t1<<<BB * FF / 256, 256>>>(pt1);
    smallgemm_kernel<<<dim3(FF / 256, BB, 4), 256>>>(h_out, w1, pt1);
    // join side stream, then L_pre = tanh(A@w2 + t1 + bias) . v
    cudaStreamWaitEvent(0, e2, 0);
    gemm_mma<2><<<tgrid, 256, SMEM_GEMM>>>(pAh, pW2h, attn_bias,
                                           nullptr, nullptr, pt1, v, pLpre,
                                           nullptr, nullptr);
    // sparsemax
    sparsemax_kernel<<<BB, 1024>>>(pLpre, mask, w_1, w_2s, w_3, layer_i, L_out);
}

// round 8
// speedup vs baseline: 6.2513x; 1.0228x over previous
#include <cuda_runtime.h>
#include <cuda_fp16.h>
#include <math.h>
#include <stdint.h>

#define BB 16
#define SS 2048
#define HH 1024
#define FF 1024
#define MM (BB*SS)   // 32768

// ---------------- device scratch (no runtime allocation allowed) ----------
__device__ __half g_Xh[(size_t)MM*HH];
__device__ __half g_Ch[(size_t)MM*FF];
__device__ __half g_Am[(size_t)MM*FF];
__device__ __half g_P[(size_t)MM*FF];     // A@w2 + attn_bias (fp16)
__device__ __half g_WCh[(size_t)FF*HH];
__device__ __half g_WAh[(size_t)FF*HH];
__device__ __half g_W2h[(size_t)FF*FF];
__device__ float g_q[BB*FF];
__device__ float g_t1[BB*FF];
__device__ float g_pre[BB*SS];
__device__ float g_alpha[BB*SS];
__device__ float g_Lpre[BB*SS];

// ---------------------------------------------------------------------------
__device__ __forceinline__ void cpa16(uint32_t s, const void* g) {
    asm volatile("cp.async.cg.shared.global [%0], [%1], 16;" :: "r"(s), "l"(g));
}
__device__ __forceinline__ void cp_commit() {
    asm volatile("cp.async.commit_group;");
}
__device__ __forceinline__ void ldsm4(uint32_t* r, uint32_t a) {
    asm volatile("ldmatrix.sync.aligned.m8n8.x4.shared.b16 {%0,%1,%2,%3}, [%4];"
        : "=r"(r[0]), "=r"(r[1]), "=r"(r[2]), "=r"(r[3]) : "r"(a));
}
__device__ __forceinline__ void mma16816(float* c, const uint32_t* a, const uint32_t* b) {
    asm volatile("mma.sync.aligned.m16n8k16.row.col.f32.f16.f16.f32 "
        "{%0,%1,%2,%3}, {%4,%5,%6,%7}, {%8,%9}, {%0,%1,%2,%3};"
        : "+f"(c[0]), "+f"(c[1]), "+f"(c[2]), "+f"(c[3])
        : "r"(a[0]), "r"(a[1]), "r"(a[2]), "r"(a[3]), "r"(b[0]), "r"(b[1]));
}

// ---------------------------------------------------------------------------
__global__ void zero_kernel(float* q, float* h_out, float* pre) {
    int i = blockIdx.x * 256 + threadIdx.x;
    if (i < BB * FF) { q[i] = 0.f; h_out[i] = 0.f; }
    if (i < BB * SS) { pre[i] = 0.f; }
}

// convert X fp32 -> fp16, 1 float4 per thread
__global__ void cvtX_kernel(const float4* __restrict__ X, __half* __restrict__ Xh) {
    size_t i = (size_t)blockIdx.x * 256 + threadIdx.x;
    float4 v = X[i];
    __half2* p = (__half2*)Xh;
    p[i*2]   = __floats2half2_rn(v.x, v.y);
    p[i*2+1] = __floats2half2_rn(v.z, v.w);
}

// transpose + convert weight: T[n][k] = fp16(W[k][n])
__global__ void transW_kernel(const float* __restrict__ W, __half* __restrict__ T) {
    __shared__ float t[32][33];
    int n0 = blockIdx.x * 32, k0 = blockIdx.y * 32;
    int x = threadIdx.x, y = threadIdx.y;   // 32x8
    #pragma unroll
    for (int d = 0; d < 32; d += 8)
        t[y + d][x] = W[(size_t)(k0 + y + d) * FF + n0 + x];
    __syncthreads();
    #pragma unroll
    for (int d = 0; d < 32; d += 8) {
        int n = n0 + y + d, k = k0 + x;
        T[(size_t)n * HH + k] = __float2half(t[x][y + d]);
    }
}

// ---------------------------------------------------------------------------
// HMMA fp16 GEMM:  D[M,N] = A[M,K] @ B^T[N,K]
// CTA tile 256x128x64, 8 warps (4M x 2N), warp tile 64x64, 3-stage cp.async.
// MODE 0: relu(acc+bias) -> fp16 out; fused q[b,f] += relu * iw[row]
// MODE 1: relu(acc+bias) -> fp32 out + fp16 out
// MODE 2: p = sum_n tanh(acc + t1[b,n] + bias[n]) * v[n]; atomicAdd(rowdot[m], p)
// MODE 3: (acc+bias) -> fp16 out (no relu)
#define KC 64
#define ROWB 144
#define OFF_A 0
#define OFF_B 36864
#define STAGE_B 55296
#define NSTAGE 3
#define QS_OFF (NSTAGE*STAGE_B)
#define SMEM_GEMM (QS_OFF + 512)   // 166400
#define NCHUNK (HH/KC)             // 16

template <int MODE>
__global__ void __launch_bounds__(256, 1)
gemm_mma(const __half* __restrict__ A_g, const __half* __restrict__ B_g,
         const float* __restrict__ bias,
         float* __restrict__ out_f32, __half* __restrict__ out_h,
         const float* __restrict__ t1, const float* __restrict__ vvec,
         float* __restrict__ rowdot,
         const float* __restrict__ iw, float* __restrict__ q_out)
{
    extern __shared__ char smem[];
    uint32_t sb = (uint32_t)__cvta_generic_to_shared(smem);
    int tid = threadIdx.x, lane = tid & 31, wid = tid >> 5;
    int bn = blockIdx.x, bm = blockIdx.y;

    const __half* Asrc = A_g + (size_t)bm * 256 * HH;
    const __half* Bsrc = B_g + (size_t)bn * 128 * HH;

    int ld_row = tid >> 3;          // 0..31
    int ld_ch  = tid & 7;           // 0..7 (16B chunks)

    // prologue: stages 0, 1
    #pragma unroll
    for (int c = 0; c < NSTAGE - 1; c++) {
        uint32_t buf = sb + c * STAGE_B;
        #pragma unroll
        for (int i = 0; i < 8; i++) {
            int row = ld_row + i * 32;
            cpa16(buf + OFF_A + row * ROWB + ld_ch * 16,
                  Asrc + (size_t)row * HH + c * KC + ld_ch * 8);
        }
        #pragma unroll
        for (int i = 0; i < 4; i++) {
            int row = ld_row + i * 32;
            cpa16(buf + OFF_B + row * ROWB + ld_ch * 16,
                  Bsrc + (size_t)row * HH + c * KC + ld_ch * 8);
        }
        cp_commit();
    }

    float acc[4][8][4];
    #pragma unroll
    for (int mt = 0; mt < 4; mt++)
        #pragma unroll
        for (int nt = 0; nt < 8; nt++)
            #pragma unroll
            for (int e = 0; e < 4; e++) acc[mt][nt][e] = 0.f;

    int warpM = wid & 3, warpN = wid >> 2;
    int m0 = warpM * 64, n0 = warpN * 64;

    uint32_t a_base = (uint32_t)(m0 + (lane & 15)) * ROWB + (uint32_t)(lane >> 4) * 16;
    int b_rowp = ((lane >> 4) << 3) + (lane & 7);
    uint32_t b_base = (uint32_t)(n0 + b_rowp) * ROWB + (uint32_t)((lane >> 3) & 1) * 16;

    for (int c = 0; c < NCHUNK; c++) {
        if (c < NCHUNK - 2) asm volatile("cp.async.wait_group 1;" ::: "memory");
        else                asm volatile("cp.async.wait_group 0;" ::: "memory");
        __syncthreads();

        if (c + NSTAGE - 1 < NCHUNK) {
            uint32_t buf = sb + ((c + NSTAGE - 1) % NSTAGE) * STAGE_B;
            int kc0 = (c + NSTAGE - 1) * KC;
            #pragma unroll
            for (int i = 0; i < 8; i++) {
                int row = ld_row + i * 32;
                cpa16(buf + OFF_A + row * ROWB + ld_ch * 16,
                      Asrc + (size_t)row * HH + kc0 + ld_ch * 8);
            }
            #pragma unroll
            for (int i = 0; i < 4; i++) {
                int row = ld_row + i * 32;
                cpa16(buf + OFF_B + row * ROWB + ld_ch * 16,
                      Bsrc + (size_t)row * HH + kc0 + ld_ch * 8);
            }
        }
        cp_commit();

        uint32_t buf = sb + (c % NSTAGE) * STAGE_B;
        uint32_t As = buf + OFF_A, Bs = buf + OFF_B;

        #pragma unroll
        for (int ks = 0; ks < 4; ks++) {
            uint32_t ah[4][4];
            #pragma unroll
            for (int mt = 0; mt < 4; mt++)
                ldsm4(ah[mt], As + a_base + (uint32_t)mt * (16 * ROWB) + (uint32_t)ks * 32);
            uint32_t bh[8][2];
            #pragma unroll
            for (int p = 0; p < 4; p++) {
                uint32_t r[4];
                ldsm4(r, Bs + b_base + (uint32_t)p * (16 * ROWB) + (uint32_t)ks * 32);
                bh[2*p][0] = r[0]; bh[2*p][1] = r[1];
                bh[2*p+1][0] = r[2]; bh[2*p+1][1] = r[3];
            }
            #pragma unroll
            for (int mt = 0; mt < 4; mt++)
                #pragma unroll
                for (int nt = 0; nt < 8; nt++)
                    mma16816(acc[mt][nt], ah[mt], bh[nt]);
        }
    }

    // ---------------- epilogue ----------------
    int g4 = lane >> 2;           // row-in-8 group
    int cpair = (lane & 3) * 2;   // col pair base

    if (MODE == 2) {
        int batch = bm >> 3;      // 256 rows per bm; 2048 per batch
        #pragma unroll
        for (int mt = 0; mt < 4; mt++) {
            #pragma unroll
            for (int h = 0; h < 2; h++) {
                int grow = bm * 256 + m0 + mt * 16 + g4 + h * 8;
                float p = 0.f;
                #pragma unroll
                for (int nt = 0; nt < 8; nt++) {
                    int n = bn * 128 + n0 + nt * 8 + cpair;
                    #pragma unroll
                    for (int e = 0; e < 2; e++) {
                        float x = acc[mt][nt][h * 2 + e] + t1[batch * FF + n + e] + bias[n + e];
                        p = fmaf(tanhf(x), vvec[n + e], p);
                    }
                }
                p += __shfl_xor_sync(0xffffffffu, p, 1);
                p += __shfl_xor_sync(0xffffffffu, p, 2);
                if ((lane & 3) == 0) atomicAdd(&rowdot[grow], p);
            }
        }
    } else {
        #pragma unroll
        for (int mt = 0; mt < 4; mt++) {
            #pragma unroll
            for (int h = 0; h < 2; h++) {
                int grow = bm * 256 + m0 + mt * 16 + g4 + h * 8;
                #pragma unroll
                for (int nt = 0; nt < 8; nt++) {
                    int n = bn * 128 + n0 + nt * 8 + cpair;
                    float v0 = acc[mt][nt][h * 2 + 0] + bias[n + 0];
                    float v1 = acc[mt][nt][h * 2 + 1] + bias[n + 1];
                    if (MODE != 3) {
                        v0 = v0 > 0.f ? v0 : 0.f;
                        v1 = v1 > 0.f ? v1 : 0.f;
                    }
                    if (MODE == 1)
                        *(float2*)(out_f32 + (size_t)grow * FF + n) = make_float2(v0, v1);
                    *(__half2*)(out_h + (size_t)grow * FF + n) = __floats2half2_rn(v0, v1);
                }
            }
        }
        if (MODE == 0) {
            // fused q[b,f] += sum_rows relu(acc+bias) * iw[row]
            float* qs_red = (float*)(smem + QS_OFF);
            if (tid < 128) qs_red[tid] = 0.f;
            __syncthreads();
            float iwv[4][2];
            #pragma unroll
            for (int mt = 0; mt < 4; mt++)
                #pragma unroll
                for (int h = 0; h < 2; h++)
                    iwv[mt][h] = iw[bm * 256 + m0 + mt * 16 + g4 + h * 8];
            #pragma unroll
            for (int nt = 0; nt < 8; nt++) {
                #pragma unroll
                for (int e = 0; e < 2; e++) {
                    int n = bn * 128 + n0 + nt * 8 + cpair + e;
                    float p = 0.f;
                    #pragma unroll
                    for (int mt = 0; mt < 4; mt++)
                        #pragma unroll
                        for (int h = 0; h < 2; h++) {
                            float vv = acc[mt][nt][h * 2 + e] + bias[n];
                            vv = vv > 0.f ? vv : 0.f;
                            p = fmaf(vv, iwv[mt][h], p);
                        }
                    p += __shfl_xor_sync(0xffffffffu, p, 4);
                    p += __shfl_xor_sync(0xffffffffu, p, 8);
                    p += __shfl_xor_sync(0xffffffffu, p, 16);
                    if (g4 == 0)
                        atomicAdd(&qs_red[n0 + nt * 8 + cpair + e], p);
                }
            }
            __syncthreads();
            if (tid < 128)
                atomicAdd(&q_out[(bm >> 3) * FF + bn * 128 + tid], qs_red[tid]);
        }
    }
}

// ---------------------------------------------------------------------------
// Lpre[m] = sum_n tanh(P[m,n] + t1[b,n]) * v[n]   (one warp per row)
__global__ void lpre_epi(const __half* __restrict__ P,
                         const float* __restrict__ t1,
                         const float* __restrict__ vvec,
                         float* __restrict__ Lpre)
{
    int m = (blockIdx.x * 256 + threadIdx.x) >> 5;
    int lane = threadIdx.x & 31;
    int b = m >> 11;
    const __half2* pp = (const __half2*)(P + (size_t)m * FF);
    const float* tb = t1 + b * FF;
    float acc = 0.f;
    #pragma unroll
    for (int k = 0; k < 16; k++) {
        int idx = lane + k * 32;          // half2 index, 0..511
        float2 pv = __half22float2(pp[idx]);
        int n = idx * 2;
        acc = fmaf(tanhf(pv.x + tb[n]),     vvec[n],     acc);
        acc = fmaf(tanhf(pv.y + tb[n + 1]), vvec[n + 1], acc);
    }
    #pragma unroll
    for (int o = 16; o; o >>= 1)
        acc += __shfl_down_sync(0xffffffffu, acc, o);
    if (lane == 0) Lpre[m] = acc;
}

// ---------------------------------------------------------------------------
// out[b,f] += sum_s X[b,s,f] * w[b,s]  — 2 columns per thread via __half2
__global__ void colreduce_h(const __half* __restrict__ Xh,
                            const float* __restrict__ w,
                            float* __restrict__ out)
{
    int f2 = blockIdx.x * 256 + threadIdx.x;   // pair index, 0..511
    int b = blockIdx.y;
    int s0 = blockIdx.z * 256;
    const __half2* hp = (const __half2*)(Xh + ((size_t)b * SS + s0) * FF) + f2;
    const float* wp = w + b * SS + s0;
    float a0 = 0.f, a1 = 0.f;
    #pragma unroll 4
    for (int s = 0; s < 256; s++) {
        float2 cv = __half22float2(hp[(size_t)s * (FF/2)]);
        float ww = wp[s];
        a0 = fmaf(cv.x, ww, a0);
        a1 = fmaf(cv.y, ww, a1);
    }
    atomicAdd(&out[b * FF + f2 * 2], a0);
    atomicAdd(&out[b * FF + f2 * 2 + 1], a1);
}

// t1[b,n] += sum_k q[b,k0+k] * w1[k0+k,n]   (k-split via blockIdx.z, atomic)
__global__ void smallgemm_kernel(const float* __restrict__ q,
                                 const float* __restrict__ w1,
                                 float* __restrict__ t1)
{
    __shared__ float qs[256];
    int n = blockIdx.x * 256 + threadIdx.x;
    int b = blockIdx.y;
    int k0 = blockIdx.z * 256;
    qs[threadIdx.x] = q[b * FF + k0 + threadIdx.x];
    __syncthreads();
    float acc = 0.f;
    #pragma unroll 8
    for (int k = 0; k < 256; k++)
        acc = fmaf(qs[k], w1[(size_t)(k0 + k) * FF + n], acc);
    atomicAdd(&t1[b * FF + n], acc);
}

__global__ void zero_t1(float* t1) {
    t1[blockIdx.x * 256 + threadIdx.x] = 0.f;
}

// ---------------------------------------------------------------------------
__device__ __forceinline__ float blockReduce(float v, bool do_max) {
    __shared__ float sm[32];
    __syncthreads();
    int lane = threadIdx.x & 31, wid = threadIdx.x >> 5;
    #pragma unroll
    for (int o = 16; o; o >>= 1) {
        float t = __shfl_down_sync(0xffffffffu, v, o);
        v = do_max ? fmaxf(v, t) : v + t;
    }
    if (lane == 0) sm[wid] = v;
    __syncthreads();
    int nw = blockDim.x >> 5;
    v = (threadIdx.x < nw) ? sm[threadIdx.x] : (do_max ? -1e30f : 0.f);
    if (wid == 0) {
        #pragma unroll
        for (int o = 16; o; o >>= 1) {
            float t = __shfl_down_sync(0xffffffffu, v, o);
            v = do_max ? fmaxf(v, t) : v + t;
        }
        if (lane == 0) sm[0] = v;
    }
    __syncthreads();
    return sm[0];
}

__global__ void softmax_kernel(const float* __restrict__ pre,
                               const float* __restrict__ mask,
                               float* __restrict__ alpha)
{
    int b = blockIdx.x, tid = threadIdx.x;
    float z[8];
    float mx = -1e30f;
    #pragma unroll
    for (int i = 0; i < 8; i++) {
        int s = tid + i * 256;
        z[i] = pre[b * SS + s] + (1.f - mask[b * SS + s]) * -10000.f;
        mx = fmaxf(mx, z[i]);
    }
    mx = blockReduce(mx, true);
    float sum = 0.f;
    #pragma unroll
    for (int i = 0; i < 8; i++) { z[i] = expf(z[i] - mx); sum += z[i]; }
    sum = blockReduce(sum, false);
    float inv = 1.f / sum;
    #pragma unroll
    for (int i = 0; i < 8; i++)
        alpha[b * SS + tid + i * 256] = z[i] * inv;
}

__global__ void sparsemax_kernel(const float* __restrict__ Lpre,
                                 const float* __restrict__ mask,
                                 const float* __restrict__ w_1,
                                 const float* __restrict__ w_2,
                                 const float* __restrict__ w_3,
                                 const int* __restrict__ layer_i,
                                 float* __restrict__ Lout)
{
    __shared__ float zs[SS];
    __shared__ float cum[SS];
    __shared__ int scnt;
    int b = blockIdx.x, tid = threadIdx.x;

    int li = layer_i[0];
    float a1 = w_1[0], a2 = w_2[0], a3 = w_3[0];
    float x;
    if (li == 0)      x = a3 * a3 - a2 * a2 - a1 * a1;
    else if (li == 1) x = a3 * a3 - a2 * a2;
    else              x = a3 * a3;
    float sig = 1.f / (1.f + expf(-x));

    for (int i = tid; i < SS; i += 1024)
        zs[i] = Lpre[b * SS + i] * sig + (1.f - mask[b * SS + i]) * -10000.f;
    if (tid == 0) scnt = 0;
    __syncthreads();

    for (int k = 2; k <= SS; k <<= 1) {
        for (int j = k >> 1; j > 0; j >>= 1) {
            for (int t = tid; t < SS; t += 1024) {
                int ixj = t ^ j;
                if (ixj > t) {
                    float a = zs[t], c = zs[ixj];
                    bool up = ((t & k) == 0);
                    if ((a > c) == up) { zs[t] = c; zs[ixj] = a; }
                }
            }
            __syncthreads();
        }
    }

    cum[tid]        = zs[SS - 1 - tid];
    cum[tid + 1024] = zs[SS - 1 - (tid + 1024)];
    __syncthreads();
    for (int off = 1; off < SS; off <<= 1) {
        float v0 = (tid >= off) ? cum[tid - off] : 0.f;
        float v1 = cum[tid + 1024 - off];
        __syncthreads();
        cum[tid] += v0;
        cum[tid + 1024] += v1;
        __syncthreads();
    }

    int c = 0;
    #pragma unroll
    for (int r = 0; r < 2; r++) {
        int i = tid + r * 1024;
        if (1.f + (float)(i + 1) * zs[SS - 1 - i] > cum[i]) c++;
    }
    atomicAdd(&scnt, c);
    __syncthreads();
    int ks = scnt;
    float tau = (cum[ks - 1] - 1.f) / (float)ks;

    for (int i = tid; i < SS; i += 1024) {
        float zv = Lpre[b * SS + i] * sig + (1.f - mask[b * SS + i]) * -10000.f;
        Lout[b * SS + i] = fmaxf(zv - tau, 0.f);
    }
}

// ---------------------------------------------------------------------------
extern "C" void kernel_launch(void* const* d_in, const int* in_sizes, int n_in,
                              void* d_out, int out_size)
{
    const float* mask      = (const float*)d_in[0];
    const float* X         = (const float*)d_in[1];
    const float* iw        = (const float*)d_in[2];
    const float* W_C       = (const float*)d_in[3];
    const float* b_C       = (const float*)d_in[4];
    const float* W_A       = (const float*)d_in[5];
    const float* b_A       = (const float*)d_in[6];
    const float* w1        = (const float*)d_in[7];
    const float* w2        = (const float*)d_in[8];
    const float* attn_bias = (const float*)d_in[9];
    const float* v         = (const float*)d_in[10];
    const float* w_1       = (const float*)d_in[11];
    const float* w_2s      = (const float*)d_in[12];
    const float* w_3       = (const float*)d_in[13];
    const int*   layer_i   = (const int*)d_in[14];

    float* out   = (float*)d_out;
    float* h_out = out;
    float* L_out = out + BB * FF;
    float* A_out = out + BB * FF + BB * SS;

    __half *pXh, *pCh, *pAh, *pP, *pWCh, *pWAh, *pW2h;
    float *pq, *pt1, *ppre, *palpha, *pLpre;
    cudaGetSymbolAddress((void**)&pXh, g_Xh);
    cudaGetSymbolAddress((void**)&pCh, g_Ch);
    cudaGetSymbolAddress((void**)&pAh, g_Am);
    cudaGetSymbolAddress((void**)&pP,  g_P);
    cudaGetSymbolAddress((void**)&pWCh, g_WCh);
    cudaGetSymbolAddress((void**)&pWAh, g_WAh);
    cudaGetSymbolAddress((void**)&pW2h, g_W2h);
    cudaGetSymbolAddress((void**)&pq, g_q);
    cudaGetSymbolAddress((void**)&pt1, g_t1);
    cudaGetSymbolAddress((void**)&ppre, g_pre);
    cudaGetSymbolAddress((void**)&palpha, g_alpha);
    cudaGetSymbolAddress((void**)&pLpre, g_Lpre);

    cudaFuncSetAttribute(gemm_mma<0>, cudaFuncAttributeMaxDynamicSharedMemorySize, SMEM_GEMM);
    cudaFuncSetAttribute(gemm_mma<1>, cudaFuncAttributeMaxDynamicSharedMemorySize, SMEM_GEMM);
    cudaFuncSetAttribute(gemm_mma<2>, cudaFuncAttributeMaxDynamicSharedMemorySize, SMEM_GEMM);
    cudaFuncSetAttribute(gemm_mma<3>, cudaFuncAttributeMaxDynamicSharedMemorySize, SMEM_GEMM);

    dim3 tgrid(FF / 128, MM / 256);   // (8, 128) — n fastest for A-tile L2 reuse
    dim3 wgrid(FF / 32, HH / 32);

    // side stream + events for forked capture
    cudaStream_t s2;
    cudaStreamCreateWithFlags(&s2, cudaStreamNonBlocking);
    cudaEvent_t e0, e1, eW2, e2;
    cudaEventCreateWithFlags(&e0, cudaEventDisableTiming);
    cudaEventCreateWithFlags(&e1, cudaEventDisableTiming);
    cudaEventCreateWithFlags(&eW2, cudaEventDisableTiming);
    cudaEventCreateWithFlags(&e2, cudaEventDisableTiming);

    // ---- main stream: prep ----
    zero_kernel<<<128, 256>>>(pq, h_out, ppre);
    cudaEventRecord(e0, 0);                        // fork point for s2
    cvtX_kernel<<<(MM * HH / 4) / 256, 256>>>((const float4*)X, pXh);
    cudaEventRecord(e1, 0);                        // Xh ready
    transW_kernel<<<wgrid, dim3(32, 8)>>>(W_C, pWCh);
    transW_kernel<<<wgrid, dim3(32, 8)>>>(w2, pW2h);
    cudaEventRecord(eW2, 0);                       // w2^T ready

    // ---- side stream: A = relu(X@W_A + b_A), then P = A@w2 + attn_bias ----
    cudaStreamWaitEvent(s2, e0, 0);
    transW_kernel<<<wgrid, dim3(32, 8), 0, s2>>>(W_A, pWAh);
    cudaStreamWaitEvent(s2, e1, 0);
    gemm_mma<1><<<tgrid, 256, SMEM_GEMM, s2>>>(pXh, pWAh, b_A,
                                               A_out, pAh, nullptr, nullptr, nullptr,
                                               nullptr, nullptr);
    cudaStreamWaitEvent(s2, eW2, 0);
    gemm_mma<3><<<tgrid, 256, SMEM_GEMM, s2>>>(pAh, pW2h, attn_bias,
                                               nullptr, pP, nullptr, nullptr, nullptr,
                                               nullptr, nullptr);
    cudaEventRecord(e2, s2);

    // ---- main stream: C chain ----
    // C = relu(X@W_C + b_C) -> fp16; fused q = C^T @ item_weights
    gemm_mma<0><<<tgrid, 256, SMEM_GEMM>>>(pXh, pWCh, b_C,
                                           nullptr, pCh, nullptr, nullptr, nullptr,
                                           iw, pq);
    // t1 = q @ w1
    zero_t1<<<BB * FF / 256, 256>>>(pt1);
    smallgemm_kernel<<<dim3(FF / 256, BB, 4), 256>>>(pq, w1, pt1);
    // alpha_pre = tanh(C@w2 + t1 + bias) . v
    gemm_mma<2><<<tgrid, 256, SMEM_GEMM>>>(pCh, pW2h, attn_bias,
                                           nullptr, nullptr, pt1, v, ppre,
                                           nullptr, nullptr);
    // softmax
    softmax_kernel<<<BB, 256>>>(ppre, mask, palpha);
    // h = C^T @ alpha
    colreduce_h<<<dim3(FF / 512, BB, 8), 256>>>(pCh, palpha, h_out);
    // t1 = h @ w1
    zero_t1<<<BB * FF / 256, 256>>>(pt1);
    smallgemm_kernel<<<dim3(FF / 256, BB, 4), 256>>>(h_out, w1, pt1);
    // join side stream; Lpre = tanh(P + t1 + 0) . v   (bias already in P)
    cudaStreamWaitEvent(0, e2, 0);
    lpre_epi<<<MM * 32 / 256, 256>>>(pP, pt1, v, pLpre);
    // sparsemax
    sparsemax_kernel<<<BB, 1024>>>(pLpre, mask, w_1, w_2s, w_3, layer_i, L_out);
}